// round 5
// baseline (speedup 1.0000x reference)
#include <cuda_runtime.h>
#include <math.h>
#include <stdint.h>

// ---------------------------------------------------------------------------
// Problem constants
// ---------------------------------------------------------------------------
#define BSZ   16
#define LSEQ  50
#define NBLK  64
#define DM    256
#define DH    512
#define KD    768
#define NVOC  65536
#define NTOK  (BSZ*LSEQ*NBLK)   // 51200
#define NBL   (BSZ*LSEQ)        // 800
#define SLOTS (LSEQ*NBLK)       // 3200 per batch

__device__ __forceinline__ float neg_inf() { return __int_as_float(0xff800000); }

// ---------------------------------------------------------------------------
// Scratch (static device globals; no allocation)
// ---------------------------------------------------------------------------
__device__ __align__(128) float g_Hh[(size_t)NVOC*DH];  // relu hidden, tf32-hi plane
__device__ __align__(128) float g_Hl[(size_t)NVOC*DH];  // relu hidden, tf32-lo plane
__device__ __align__(128) float g_Y [(size_t)NVOC*DM];  // pre-LN
__device__ __align__(128) float g_VT [(size_t)NVOC*DM]; // v_text post-LN (raw)
__device__ __align__(128) float g_VTh[(size_t)NVOC*DM]; // v_text hi plane
__device__ __align__(128) float g_VTl[(size_t)NVOC*DM]; // v_text lo plane
__device__ __align__(128) float g_KV[(size_t)NVOC*DM];  // v_text @ wk
__device__ __align__(128) float g_S2[(size_t)NVOC*DM];  // v_text @ am_w1[D:]
__device__ __align__(128) float g_S [NTOK];
__device__ __align__(128) float g_T [NBL*DM];
__device__ __align__(128) float g_QW[NBL*DM];

// pre-split weight planes: w1 | w2 | wk | amw1[D:]
#define OFF_W1 0
#define OFF_W2 393216
#define OFF_WK 524288
#define OFF_AM 589824
#define TOTW   655360
__device__ __align__(128) float g_Bh[TOTW];
__device__ __align__(128) float g_Bl[TOTW];

__device__ int   g_present[NVOC];
__device__ int   g_cidx[NVOC];
__device__ int   g_ulist[NVOC];
__device__ int   g_ucnt[1];
__device__ int   g_tokc[NTOK];
__device__ int   g_selslot[NTOK];
__device__ int   g_fslot[BSZ*64];
__device__ int   g_fid  [BSZ*64];
__device__ __align__(128) float g_vfin[BSZ*DM];
__device__ __align__(128) float g_mfin[BSZ*DM];

// ---------------------------------------------------------------------------
// TF32 split helpers
// ---------------------------------------------------------------------------
__device__ __forceinline__ uint32_t f2tf(float x)
{
    uint32_t r;
    asm("cvt.rna.tf32.f32 %0, %1;" : "=r"(r) : "f"(x));
    return r;
}
__device__ __forceinline__ void split_tf(float x, float& hi, float& lo)
{
    uint32_t h = f2tf(x);
    hi = __uint_as_float(h);
    lo = __uint_as_float(f2tf(x - hi));
}
__device__ __forceinline__ void mma_tf32(float c[4], const uint32_t a[4], const uint32_t b[2])
{
    asm volatile(
        "mma.sync.aligned.m16n8k8.row.col.f32.tf32.tf32.f32 "
        "{%0,%1,%2,%3}, {%4,%5,%6,%7}, {%8,%9}, {%0,%1,%2,%3};"
        : "+f"(c[0]), "+f"(c[1]), "+f"(c[2]), "+f"(c[3])
        : "r"(a[0]), "r"(a[1]), "r"(a[2]), "r"(a[3]), "r"(b[0]), "r"(b[1]));
}
__device__ __forceinline__ uint32_t s2u(const void* p)
{
    return (uint32_t)__cvta_generic_to_shared(p);
}
__device__ __forceinline__ void cpasync16(uint32_t dst, const void* src)
{
    asm volatile("cp.async.ca.shared.global [%0], [%1], 16;" :: "r"(dst), "l"(src));
}
#define CP_COMMIT() asm volatile("cp.async.commit_group;")
#define CP_WAIT0()  asm volatile("cp.async.wait_group 0;")

// ---------------------------------------------------------------------------
// zero + weight split (one kernel so gemm1 sits at profiled launch index 3)
// ---------------------------------------------------------------------------
__global__ void zero_split_k(const float* __restrict__ w1, const float* __restrict__ w2,
                             const float* __restrict__ wk, const float* __restrict__ am1)
{
    int i = blockIdx.x * blockDim.x + threadIdx.x;   // 512*256 = 131072
    if (i < NVOC) { g_present[i] = 0; g_ulist[i] = 0; }
    const int STR = 131072;
    for (int j = i; j < 393216; j += STR) split_tf(w1[j], g_Bh[OFF_W1+j], g_Bl[OFF_W1+j]);
    for (int j = i; j < 131072; j += STR) split_tf(w2[j], g_Bh[OFF_W2+j], g_Bl[OFF_W2+j]);
    for (int j = i; j < 65536;  j += STR) split_tf(wk[j], g_Bh[OFF_WK+j], g_Bl[OFF_WK+j]);
    for (int j = i; j < 65536;  j += STR) split_tf(am1[j], g_Bh[OFF_AM+j], g_Bl[OFF_AM+j]);
}
__global__ void mark_k(const int* __restrict__ ids)
{
    int t = blockIdx.x * blockDim.x + threadIdx.x;
    if (t < NTOK) g_present[ids[t]] = 1;
}
// single-block scan + compact (1024 threads x 64 entries each)
__global__ void scanall_k()
{
    __shared__ int ssum[1024];
    int t = threadIdx.x;
    int base = t * 64;
    int s = 0;
    for (int j = 0; j < 64; j++) s += g_present[base + j];
    ssum[t] = s; __syncthreads();
    for (int off = 1; off < 1024; off <<= 1) {
        int v = (t >= off) ? ssum[t - off] : 0;
        __syncthreads();
        ssum[t] += v;
        __syncthreads();
    }
    int run = ssum[t] - s;
    if (t == 1023) g_ucnt[0] = ssum[t];
    for (int j = 0; j < 64; j++) {
        int g = base + j;
        int p = g_present[g];
        g_cidx[g] = run;
        if (p) g_ulist[run] = g;
        run += p;
    }
}
__global__ void tokc_k(const int* __restrict__ ids)
{
    int t = blockIdx.x * blockDim.x + threadIdx.x;
    if (t < NTOK) g_tokc[t] = g_cidx[ids[t]];
}

// ---------------------------------------------------------------------------
// Tensor-core GEMM, 2-term TF32 split (3 passes). Block tile 128x256, BK=32,
// 8 warps (2m x 4n), warp tile 64x64 (acc 128 regs). smem hi/lo planes filled
// by cp.async from pre-split gmem planes (B always; A when Ah_g given), or by
// register-load + in-thread split (gemm1's gathered embedding rows).
// dual=1: blockIdx.y selects output pair (B0->C0 / B1->C1), shared A.
// Fixed k-ascending accumulation => deterministic per gathered row.
// ---------------------------------------------------------------------------
#define A_STR 36
#define B_STR 264
#define A_TILE (128*A_STR)                // 4608 floats / plane
#define B_TILE (32*B_STR)                 // 8448 floats / plane
#define BUF_FLTS (2*A_TILE + 2*B_TILE)    // 26112
#define GEMM_SMEM (2*BUF_FLTS*4)          // 208896 B

__global__ void __launch_bounds__(256, 1) gemm_tc(
    const float* __restrict__ Araw,                    // non-null -> register A path
    const float* __restrict__ Ah_g, const float* __restrict__ Al_g,
    const float* __restrict__ Bh0, const float* __restrict__ Bl0,
    float* __restrict__ C0, const float* __restrict__ bias0,
    const float* __restrict__ Bh1, const float* __restrict__ Bl1,
    float* __restrict__ C1, const float* __restrict__ bias1,
    int Kdim, int Ndim,
    const int* __restrict__ gather,
    int act,                                           // 0=none 1=relu
    const int* __restrict__ ucntp,
    int dual,
    float* __restrict__ Ch, float* __restrict__ Cl)    // optional split-plane out
{
    extern __shared__ float sm[];
    const int bm = blockIdx.x * 128;
    if (bm >= ucntp[0]) return;

    const float *BhG, *BlG, *bias_;
    float* Cp;
    int bn;
    if (dual && blockIdx.y) { BhG = Bh1; BlG = Bl1; Cp = C1; bias_ = bias1; bn = 0; }
    else { BhG = Bh0; BlG = Bl0; Cp = C0; bias_ = bias0; bn = dual ? 0 : blockIdx.y * 256; }

    const int tid = threadIdx.x;
    const int wid = tid >> 5, lane = tid & 31;
    const int wm = (wid >> 2) * 64, wn = (wid & 3) * 64;
    const int grp = lane >> 2, qd = lane & 3;

    const int a_row  = tid >> 1, a_colh = (tid & 1) * 16;
    const int b_row  = tid >> 3, b_q    = (tid & 7) * 4;

    int ar = bm + a_row;
    if (gather) ar = gather[ar];
    const bool useAsync = (Araw == nullptr);
    const float* ApR = useAsync ? nullptr : (Araw + (size_t)ar * Kdim + a_colh);
    const float* AhR = useAsync ? (Ah_g + (size_t)ar * Kdim + a_colh) : nullptr;
    const float* AlR = useAsync ? (Al_g + (size_t)ar * Kdim + a_colh) : nullptr;
    const float* BhR = BhG + (size_t)b_row * Ndim + bn + b_q;
    const float* BlR = BlG + (size_t)b_row * Ndim + bn + b_q;

    float acc[4][8][4];
#pragma unroll
    for (int mi = 0; mi < 4; mi++)
#pragma unroll
        for (int ni = 0; ni < 8; ni++)
#pragma unroll
            for (int j = 0; j < 4; j++) acc[mi][ni][j] = 0.f;

    const int ktiles = Kdim >> 5;

    auto issueB = [&](float* buf, int kt) {
        float* BhS = buf + 2*A_TILE;
        float* BlS = BhS + B_TILE;
        const float* sh = BhR + (size_t)kt * 32 * Ndim;
        const float* sl = BlR + (size_t)kt * 32 * Ndim;
        uint32_t dh = s2u(&BhS[b_row*B_STR + b_q]);
        uint32_t dl = s2u(&BlS[b_row*B_STR + b_q]);
#pragma unroll
        for (int j = 0; j < 8; j++) {
            cpasync16(dh + j*32*4, sh + j*32);
            cpasync16(dl + j*32*4, sl + j*32);
        }
    };
    auto issueA = [&](float* buf, int kt) {
        float* AhS = buf;
        float* AlS = buf + A_TILE;
        uint32_t dh = s2u(&AhS[a_row*A_STR + a_colh]);
        uint32_t dl = s2u(&AlS[a_row*A_STR + a_colh]);
#pragma unroll
        for (int j = 0; j < 4; j++) {
            cpasync16(dh + j*16, AhR + kt*32 + j*4);
            cpasync16(dl + j*16, AlR + kt*32 + j*4);
        }
    };
    auto storeAsplit = [&](float* buf, const float4* av) {
        float* AhS = buf;
        float* AlS = buf + A_TILE;
#pragma unroll
        for (int j = 0; j < 4; j++) {
            float4 v = av[j], h4, l4;
            split_tf(v.x, h4.x, l4.x); split_tf(v.y, h4.y, l4.y);
            split_tf(v.z, h4.z, l4.z); split_tf(v.w, h4.w, l4.w);
            *(float4*)&AhS[a_row*A_STR + a_colh + j*4] = h4;
            *(float4*)&AlS[a_row*A_STR + a_colh + j*4] = l4;
        }
    };

    // prologue
    if (useAsync) issueA(sm, 0);
    else {
        float4 av[4];
#pragma unroll
        for (int j = 0; j < 4; j++) av[j] = *(const float4*)(ApR + j*4);
        storeAsplit(sm, av);
    }
    issueB(sm, 0);
    CP_COMMIT(); CP_WAIT0();
    __syncthreads();

    for (int kt = 0; kt < ktiles; kt++) {
        float* cur = sm + (kt & 1) * BUF_FLTS;
        float* nxt = sm + ((kt & 1) ^ 1) * BUF_FLTS;
        const bool more = (kt + 1 < ktiles);
        float4 avn[4];
        if (more) {
            if (useAsync) issueA(nxt, kt + 1);
            else {
#pragma unroll
                for (int j = 0; j < 4; j++) avn[j] = *(const float4*)(ApR + (kt+1)*32 + j*4);
            }
            issueB(nxt, kt + 1);
            CP_COMMIT();
        }

        const float* Ah = cur;
        const float* Al = cur + A_TILE;
        const float* Bh = cur + 2*A_TILE;
        const float* Bl = cur + 2*A_TILE + B_TILE;

#pragma unroll
        for (int k8 = 0; k8 < 4; k8++) {
            const int c0 = k8*8 + qd, c1 = c0 + 4;
            uint32_t ah[4][4], al[4][4];
#pragma unroll
            for (int mi = 0; mi < 4; mi++) {
                const int r0 = wm + mi*16 + grp, r1 = r0 + 8;
                ah[mi][0] = __float_as_uint(Ah[r0*A_STR + c0]);
                ah[mi][1] = __float_as_uint(Ah[r1*A_STR + c0]);
                ah[mi][2] = __float_as_uint(Ah[r0*A_STR + c1]);
                ah[mi][3] = __float_as_uint(Ah[r1*A_STR + c1]);
                al[mi][0] = __float_as_uint(Al[r0*A_STR + c0]);
                al[mi][1] = __float_as_uint(Al[r1*A_STR + c0]);
                al[mi][2] = __float_as_uint(Al[r0*A_STR + c1]);
                al[mi][3] = __float_as_uint(Al[r1*A_STR + c1]);
            }
#pragma unroll
            for (int ni = 0; ni < 8; ni++) {
                const int n = wn + ni*8 + grp;
                uint32_t bh[2], bl2[2];
                bh[0]  = __float_as_uint(Bh[c0*B_STR + n]);
                bh[1]  = __float_as_uint(Bh[c1*B_STR + n]);
                bl2[0] = __float_as_uint(Bl[c0*B_STR + n]);
                bl2[1] = __float_as_uint(Bl[c1*B_STR + n]);
#pragma unroll
                for (int mi = 0; mi < 4; mi++) {
                    mma_tf32(acc[mi][ni], ah[mi], bh);
                    mma_tf32(acc[mi][ni], al[mi], bh);
                    mma_tf32(acc[mi][ni], ah[mi], bl2);
                }
            }
        }

        if (more) {
            if (!useAsync) storeAsplit(nxt, avn);
            CP_WAIT0();
        }
        __syncthreads();
    }

    // epilogue
#pragma unroll
    for (int mi = 0; mi < 4; mi++) {
        const int r0 = bm + wm + mi*16 + grp;
#pragma unroll
        for (int ni = 0; ni < 8; ni++) {
            const int n = bn + wn + ni*8 + qd*2;
            float b0 = bias_ ? bias_[n]   : 0.f;
            float b1 = bias_ ? bias_[n+1] : 0.f;
            float v0 = acc[mi][ni][0] + b0, v1 = acc[mi][ni][1] + b1;
            float v2 = acc[mi][ni][2] + b0, v3 = acc[mi][ni][3] + b1;
            if (act == 1) {
                v0 = fmaxf(v0, 0.f); v1 = fmaxf(v1, 0.f);
                v2 = fmaxf(v2, 0.f); v3 = fmaxf(v3, 0.f);
            }
            if (Cp) {
                *(float2*)&Cp[(size_t)r0 * Ndim + n]     = make_float2(v0, v1);
                *(float2*)&Cp[(size_t)(r0+8) * Ndim + n] = make_float2(v2, v3);
            }
            if (Ch) {
                float h0,l0,h1,l1,h2,l2,h3,l3;
                split_tf(v0,h0,l0); split_tf(v1,h1,l1);
                split_tf(v2,h2,l2); split_tf(v3,h3,l3);
                *(float2*)&Ch[(size_t)r0 * Ndim + n]     = make_float2(h0, h1);
                *(float2*)&Ch[(size_t)(r0+8) * Ndim + n] = make_float2(h2, h3);
                *(float2*)&Cl[(size_t)r0 * Ndim + n]     = make_float2(l0, l1);
                *(float2*)&Cl[(size_t)(r0+8) * Ndim + n] = make_float2(l2, l3);
            }
        }
    }
}

// ---------------------------------------------------------------------------
// LayerNorm: one warp per unique row; writes raw VT + split planes.
// ---------------------------------------------------------------------------
__global__ void ln_k2(const float* __restrict__ gamma, const float* __restrict__ beta,
                      const int* __restrict__ ucntp)
{
    int row  = blockIdx.x * 8 + (threadIdx.x >> 5);
    int lane = threadIdx.x & 31;
    if (row >= ucntp[0]) return;
    const float4* y4 = (const float4*)(g_Y + (size_t)row * DM);
    float4 v0 = y4[lane], v1 = y4[lane + 32];
    float s = v0.x+v0.y+v0.z+v0.w + v1.x+v1.y+v1.z+v1.w;
    for (int o = 16; o > 0; o >>= 1) s += __shfl_xor_sync(0xffffffffu, s, o);
    float mu = s * (1.f/DM);
    float4 c0 = make_float4(v0.x-mu, v0.y-mu, v0.z-mu, v0.w-mu);
    float4 c1 = make_float4(v1.x-mu, v1.y-mu, v1.z-mu, v1.w-mu);
    float q = c0.x*c0.x+c0.y*c0.y+c0.z*c0.z+c0.w*c0.w
            + c1.x*c1.x+c1.y*c1.y+c1.z*c1.z+c1.w*c1.w;
    for (int o = 16; o > 0; o >>= 1) q += __shfl_xor_sync(0xffffffffu, q, o);
    float is = rsqrtf(q * (1.f/DM) + 1e-5f);
    const float4* g4 = (const float4*)gamma;
    const float4* b4 = (const float4*)beta;
    float4 ga = g4[lane], gb = g4[lane+32], ba = b4[lane], bb = b4[lane+32];
    float4 o0 = make_float4(ga.x*c0.x*is+ba.x, ga.y*c0.y*is+ba.y,
                            ga.z*c0.z*is+ba.z, ga.w*c0.w*is+ba.w);
    float4 o1 = make_float4(gb.x*c1.x*is+bb.x, gb.y*c1.y*is+bb.y,
                            gb.z*c1.z*is+bb.z, gb.w*c1.w*is+bb.w);
    float4* vt4 = (float4*)(g_VT + (size_t)row * DM);
    vt4[lane] = o0; vt4[lane + 32] = o1;
    float4 h0, l0, h1, l1;
    split_tf(o0.x,h0.x,l0.x); split_tf(o0.y,h0.y,l0.y);
    split_tf(o0.z,h0.z,l0.z); split_tf(o0.w,h0.w,l0.w);
    split_tf(o1.x,h1.x,l1.x); split_tf(o1.y,h1.y,l1.y);
    split_tf(o1.z,h1.z,l1.z); split_tf(o1.w,h1.w,l1.w);
    float4* vh = (float4*)(g_VTh + (size_t)row * DM);
    float4* vl = (float4*)(g_VTl + (size_t)row * DM);
    vh[lane] = h0; vh[lane + 32] = h1;
    vl[lane] = l0; vl[lane + 32] = l1;
}

// ---------------------------------------------------------------------------
// Per-(b,l) precompute
// ---------------------------------------------------------------------------
__global__ void prep_k(const float* __restrict__ v, const float* __restrict__ tv,
                       const float* __restrict__ am_w1, const float* __restrict__ am_b1,
                       const float* __restrict__ wq)
{
    __shared__ float tvs[DM];
    __shared__ float qs[DM];
    int bl = blockIdx.x, d = threadIdx.x;
    float t0 = tv[(size_t)bl*DM + d];
    tvs[d] = t0;
    qs[d]  = t0 + v[(size_t)bl*DM + d];
    __syncthreads();
    float t = am_b1[d], q = 0.f;
    for (int k = 0; k < DM; k++) {
        t = fmaf(tvs[k], am_w1[k*DM + d], t);
        q = fmaf(qs[k],  wq  [k*DM + d], q);
    }
    g_T [(size_t)bl*DM + d] = t;
    g_QW[(size_t)bl*DM + d] = q;
}

// ---------------------------------------------------------------------------
// Per-token score
// ---------------------------------------------------------------------------
__global__ void score2_k(const float* __restrict__ am_w2)
{
    int tok  = blockIdx.x * 8 + (threadIdx.x >> 5);
    int lane = threadIdx.x & 31;
    int c  = g_tokc[tok];
    int bl = tok >> 6;
    const float* s2 = g_S2 + (size_t)c * DM;
    const float* tt = g_T  + (size_t)bl * DM;
    float s = 0.f;
#pragma unroll
    for (int d = lane; d < DM; d += 32)
        s = fmaf(tanhf(s2[d] + tt[d]), am_w2[d], s);
    for (int o = 16; o > 0; o >>= 1) s += __shfl_down_sync(0xffffffffu, s, o);
    if (lane == 0) g_S[tok] = s;
}

// ---------------------------------------------------------------------------
// Per-visit stable sort (softmax->mask->top_k(64 of 64) equivalent)
// ---------------------------------------------------------------------------
__global__ void select_k(const int* __restrict__ masks)
{
    int bl = blockIdx.x, j = threadIdx.x;
    __shared__ float key[64];
    int tok = bl*64 + j;
    float k_ = masks[tok] ? g_S[tok] : neg_inf();
    key[j] = k_; __syncthreads();
    int rank = 0;
    for (int m = 0; m < 64; m++) {
        float o = key[m];
        rank += (o > k_) || (o == k_ && m < j);
    }
    g_selslot[bl*64 + rank] = (bl % LSEQ) * NBLK + j;
}

// ---------------------------------------------------------------------------
// Sequential memory recurrence
// ---------------------------------------------------------------------------
__global__ void recur_k(const int* __restrict__ ids, const int* __restrict__ masks,
                        const int* __restrict__ lens)
{
    int b = blockIdx.x, tid = threadIdx.x;
    __shared__ __align__(16) float qw[DM];
    __shared__ int cslot[64], cmask[64];
    __shared__ int nslot[64], nmask[64];
    __shared__ int dslot[128], dmask[128], dcid[128];
    __shared__ float ev[128];

    if (tid < 64) {
        int slot = g_selslot[(b*LSEQ + 0)*64 + tid];
        cslot[tid] = slot;
        cmask[tid] = masks[b*SLOTS + slot];
    }
    int lb = lens[b];
    __syncthreads();

    for (int t = 1; t < LSEQ; t++) {
        qw[tid] = g_QW[(size_t)(b*LSEQ + t)*DM + tid];
        if (tid < 128) {
            int slot = (tid < 64) ? cslot[tid] : g_selslot[(b*LSEQ + t)*64 + (tid - 64)];
            dslot[tid] = slot;
            dmask[tid] = (tid < 64) ? cmask[tid] : masks[b*SLOTS + slot];
            dcid [tid] = g_tokc[b*SLOTS + slot];
        }
        __syncthreads();

        int w = tid >> 5, lane = tid & 31;
        for (int c = w; c < 128; c += 8) {
            const float4* kv = (const float4*)(g_KV + (size_t)dcid[c] * DM);
            const float4* q4 = (const float4*)qw;
            float4 k0 = kv[lane*2], k1 = kv[lane*2 + 1];
            float4 q0 = q4[lane*2], q1 = q4[lane*2 + 1];
            float s = k0.x*q0.x + k0.y*q0.y + k0.z*q0.z + k0.w*q0.w
                    + k1.x*q1.x + k1.y*q1.y + k1.z*q1.z + k1.w*q1.w;
            for (int o = 16; o > 0; o >>= 1) s += __shfl_down_sync(0xffffffffu, s, o);
            if (lane == 0) ev[c] = s;
        }
        __syncthreads();

        if (tid < 128) {
            float k_ = dmask[tid] ? ev[tid] : neg_inf();
            int rank = 0;
            for (int m = 0; m < 128; m++) {
                float o = dmask[m] ? ev[m] : neg_inf();
                rank += (o > k_) || (o == k_ && m < tid);
            }
            if (rank < 64) { nslot[rank] = dslot[tid]; nmask[rank] = dmask[tid]; }
        }
        __syncthreads();
        if (tid < 64) {
            cslot[tid] = nslot[tid];
            cmask[tid] = nmask[tid];
            if (t == lb - 1) g_fslot[b*64 + tid] = nslot[tid];
        }
        __syncthreads();
    }
}

// ---------------------------------------------------------------------------
// Pools
// ---------------------------------------------------------------------------
__global__ void final_k(const float* __restrict__ tv, const int* __restrict__ ids,
                        const int* __restrict__ lens)
{
    int b = blockIdx.x, d = threadIdx.x;
    int lb = lens[b];
    float mx = neg_inf();
    for (int l = 0; l < lb; l++) mx = fmaxf(mx, tv[((size_t)b*LSEQ + l)*DM + d]);
    g_vfin[b*DM + d] = mx;
    float mv = neg_inf();
    for (int m = 0; m < 64; m++) {
        int c = g_tokc[b*SLOTS + g_fslot[b*64 + m]];
        mv = fmaxf(mv, g_VT[(size_t)c*DM + d]);
    }
    g_mfin[b*DM + d] = mv;
    if (d < 64) g_fid[b*64 + d] = ids[b*SLOTS + g_fslot[b*64 + d]];
}

// ---------------------------------------------------------------------------
// Output head + flatten
// ---------------------------------------------------------------------------
__global__ void out_k(const float* __restrict__ ow, const float* __restrict__ ob,
                      float* __restrict__ out, int out_size)
{
    int tid = threadIdx.x;
    if (tid < 32) {
        int b = tid >> 1, o = tid & 1;
        float v = ob[o];
        for (int d = 0; d < DM; d++) v = fmaf(g_vfin[b*DM + d], ow[d*2 + o], v);
        for (int d = 0; d < DM; d++) v = fmaf(g_mfin[b*DM + d], ow[(DM + d)*2 + o], v);
        if (tid < out_size) out[tid] = v;
    }
    for (int i = tid; i < BSZ*64; i += blockDim.x)
        if (32 + i < out_size) out[32 + i] = (float)g_fid[i];
    for (int i = 32 + BSZ*64 + tid; i < out_size; i += blockDim.x)
        out[i] = 0.f;
}

// ---------------------------------------------------------------------------
// Launch
// ---------------------------------------------------------------------------
extern "C" void kernel_launch(void* const* d_in, const int* in_sizes, int n_in,
                              void* d_out, int out_size)
{
    const float* v_all  = (const float*)d_in[0];
    const float* tv_all = (const float*)d_in[1];
    const float* emb    = (const float*)d_in[2];
    const float* w1     = (const float*)d_in[3];
    const float* b1     = (const float*)d_in[4];
    const float* w2     = (const float*)d_in[5];
    const float* b2     = (const float*)d_in[6];
    const float* gam    = (const float*)d_in[7];
    const float* bet    = (const float*)d_in[8];
    const float* wq     = (const float*)d_in[9];
    const float* wk     = (const float*)d_in[10];
    const float* amw1   = (const float*)d_in[11];
    const float* amb1   = (const float*)d_in[12];
    const float* amw2   = (const float*)d_in[13];
    const float* ow     = (const float*)d_in[14];
    const float* ob     = (const float*)d_in[15];
    const int*   itxt   = (const int*)d_in[16];
    const int*   mtxt   = (const int*)d_in[17];
    const int*   lens   = (const int*)d_in[18];
    float* out = (float*)d_out;

    float *pHh, *pHl, *pY, *pVTh, *pVTl, *pKV, *pS2, *pBh, *pBl;
    int *pU, *pUL;
    cudaGetSymbolAddress((void**)&pHh, g_Hh);
    cudaGetSymbolAddress((void**)&pHl, g_Hl);
    cudaGetSymbolAddress((void**)&pY,  g_Y);
    cudaGetSymbolAddress((void**)&pVTh, g_VTh);
    cudaGetSymbolAddress((void**)&pVTl, g_VTl);
    cudaGetSymbolAddress((void**)&pKV, g_KV);
    cudaGetSymbolAddress((void**)&pS2, g_S2);
    cudaGetSymbolAddress((void**)&pBh, g_Bh);
    cudaGetSymbolAddress((void**)&pBl, g_Bl);
    cudaGetSymbolAddress((void**)&pU,  g_ucnt);
    cudaGetSymbolAddress((void**)&pUL, g_ulist);

    cudaFuncSetAttribute(gemm_tc, cudaFuncAttributeMaxDynamicSharedMemorySize, GEMM_SMEM);

    // 0..2: dedup (gemm1 lands at profiled launch index 3)
    zero_split_k<<<512, 256>>>(w1, w2, wk, amw1 + DM*DM);
    mark_k<<<NTOK/256, 256>>>(itxt);
    scanall_k<<<1, 1024>>>();

    // 3: GEMM1: relu(emb[gather] @ w1 + b1) -> split planes g_Hh/g_Hl
    gemm_tc<<<dim3(NVOC/128, 2), 256, GEMM_SMEM>>>(
        emb, nullptr, nullptr,
        pBh + OFF_W1, pBl + OFF_W1, nullptr, b1,
        nullptr, nullptr, nullptr, nullptr,
        KD, DH, pUL, 1, pU, 0, pHh, pHl);

    tokc_k<<<NTOK/256, 256>>>(itxt);
    prep_k<<<NBL, DM>>>(v_all, tv_all, amw1, amb1, wq);

    // GEMM2: Y = Hplanes @ w2 + b2
    gemm_tc<<<dim3(NVOC/128, 1), 256, GEMM_SMEM>>>(
        nullptr, pHh, pHl,
        pBh + OFF_W2, pBl + OFF_W2, pY, b2,
        nullptr, nullptr, nullptr, nullptr,
        DH, DM, nullptr, 0, pU, 0, nullptr, nullptr);

    ln_k2<<<NVOC/8, 256>>>(gam, bet, pU);

    // GEMM3+4 fused: KV = VT @ wk ; S2 = VT @ am_w1[D:]
    gemm_tc<<<dim3(NVOC/128, 2), 256, GEMM_SMEM>>>(
        nullptr, pVTh, pVTl,
        pBh + OFF_WK, pBl + OFF_WK, pKV, nullptr,
        pBh + OFF_AM, pBl + OFF_AM, pS2, nullptr,
        DM, DM, nullptr, 0, pU, 1, nullptr, nullptr);

    // score + selection + recurrence + pooling + head
    score2_k<<<NTOK/8, 256>>>(amw2);
    select_k<<<NBL, 64>>>(mtxt);
    recur_k<<<BSZ, 256>>>(itxt, mtxt, lens);
    final_k<<<BSZ, DM>>>(tv_all, itxt, lens);
    out_k<<<1, 256>>>(ow, ob, out, out_size);
}

// round 6
// speedup vs baseline: 1.3531x; 1.3531x over previous
#include <cuda_runtime.h>
#include <cuda_bf16.h>
#include <math.h>
#include <stdint.h>

// ---------------------------------------------------------------------------
// Problem constants
// ---------------------------------------------------------------------------
#define BSZ   16
#define LSEQ  50
#define NBLK  64
#define DM    256
#define DH    512
#define KD    768
#define NVOC  65536
#define NTOK  (BSZ*LSEQ*NBLK)   // 51200
#define NBL   (BSZ*LSEQ)        // 800
#define SLOTS (LSEQ*NBLK)       // 3200 per batch

typedef __nv_bfloat16 bf16;

__device__ __forceinline__ float neg_inf() { return __int_as_float(0xff800000); }

// ---------------------------------------------------------------------------
// Scratch (static device globals; no allocation)
// ---------------------------------------------------------------------------
__device__ __align__(128) bf16  g_Hh[(size_t)NVOC*DH];  // relu hidden, bf16-hi
__device__ __align__(128) bf16  g_Hl[(size_t)NVOC*DH];  // relu hidden, bf16-lo
__device__ __align__(128) float g_Y [(size_t)NVOC*DM];  // pre-LN
__device__ __align__(128) float g_VT [(size_t)NVOC*DM]; // v_text post-LN (raw)
__device__ __align__(128) bf16  g_VTh[(size_t)NVOC*DM]; // v_text hi
__device__ __align__(128) bf16  g_VTl[(size_t)NVOC*DM]; // v_text lo
__device__ __align__(128) float g_KV[(size_t)NVOC*DM];  // v_text @ wk
__device__ __align__(128) float g_S2[(size_t)NVOC*DM];  // v_text @ am_w1[D:]
__device__ __align__(128) float g_S [NTOK];
__device__ __align__(128) float g_T [NBL*DM];
__device__ __align__(128) float g_QW[NBL*DM];

// pre-split TRANSPOSED weight planes ([N][K], k-contiguous): w1 | w2 | wk | am
#define OFF_W1 0
#define OFF_W2 393216
#define OFF_WK 524288
#define OFF_AM 589824
#define TOTW   655360
__device__ __align__(128) bf16 g_Bh[TOTW];
__device__ __align__(128) bf16 g_Bl[TOTW];

__device__ int   g_present[NVOC];
__device__ int   g_cidx[NVOC];
__device__ int   g_ulist[NVOC];
__device__ int   g_ucnt[1];
__device__ int   g_tokc[NTOK];
__device__ int   g_selslot[NTOK];
__device__ int   g_fslot[BSZ*64];
__device__ int   g_fid  [BSZ*64];
__device__ __align__(128) float g_vfin[BSZ*DM];
__device__ __align__(128) float g_mfin[BSZ*DM];

// ---------------------------------------------------------------------------
// helpers
// ---------------------------------------------------------------------------
__device__ __forceinline__ void split_bf(float x, bf16& h, bf16& l)
{
    h = __float2bfloat16_rn(x);
    l = __float2bfloat16_rn(x - __bfloat162float(h));
}
__device__ __forceinline__ uint32_t pack2(bf16 a, bf16 b)
{
    return (uint32_t)__bfloat16_as_ushort(a) | ((uint32_t)__bfloat16_as_ushort(b) << 16);
}
__device__ __forceinline__ void mma_bf16(float c[4], const uint32_t a[4],
                                         uint32_t b0, uint32_t b1)
{
    asm volatile(
        "mma.sync.aligned.m16n8k16.row.col.f32.bf16.bf16.f32 "
        "{%0,%1,%2,%3}, {%4,%5,%6,%7}, {%8,%9}, {%0,%1,%2,%3};"
        : "+f"(c[0]), "+f"(c[1]), "+f"(c[2]), "+f"(c[3])
        : "r"(a[0]), "r"(a[1]), "r"(a[2]), "r"(a[3]), "r"(b0), "r"(b1));
}
__device__ __forceinline__ void ldsm_x4(uint32_t r[4], uint32_t saddr)
{
    asm volatile("ldmatrix.sync.aligned.m8n8.x4.shared.b16 {%0,%1,%2,%3}, [%4];"
        : "=r"(r[0]), "=r"(r[1]), "=r"(r[2]), "=r"(r[3]) : "r"(saddr));
}
__device__ __forceinline__ uint32_t s2u(const void* p)
{
    return (uint32_t)__cvta_generic_to_shared(p);
}
__device__ __forceinline__ void cpasync16(uint32_t dst, const void* src)
{
    asm volatile("cp.async.ca.shared.global [%0], [%1], 16;" :: "r"(dst), "l"(src));
}
#define CP_COMMIT() asm volatile("cp.async.commit_group;")
#define CP_WAIT0()  asm volatile("cp.async.wait_group 0;")

// ---------------------------------------------------------------------------
// zero + weight split+transpose ([K][N] fp32 -> [N][K] bf16 hi/lo planes)
// ---------------------------------------------------------------------------
__global__ void zero_split_k(const float* __restrict__ w1, const float* __restrict__ w2,
                             const float* __restrict__ wk, const float* __restrict__ am1)
{
    int i = blockIdx.x * blockDim.x + threadIdx.x;   // 131072 threads
    if (i < NVOC) { g_present[i] = 0; g_ulist[i] = 0; }
    const int STR = 131072;
    for (int j = i; j < 393216; j += STR) {
        int n = j / KD, k = j % KD;
        split_bf(w1[k*DH + n], g_Bh[OFF_W1+j], g_Bl[OFF_W1+j]);
    }
    for (int j = i; j < 131072; j += STR) {
        int n = j / DH, k = j % DH;
        split_bf(w2[k*DM + n], g_Bh[OFF_W2+j], g_Bl[OFF_W2+j]);
    }
    for (int j = i; j < 65536; j += STR) {
        int n = j / DM, k = j % DM;
        split_bf(wk[k*DM + n], g_Bh[OFF_WK+j], g_Bl[OFF_WK+j]);
    }
    for (int j = i; j < 65536; j += STR) {
        int n = j / DM, k = j % DM;
        split_bf(am1[k*DM + n], g_Bh[OFF_AM+j], g_Bl[OFF_AM+j]);
    }
}
__global__ void mark_k(const int* __restrict__ ids)
{
    int t = blockIdx.x * blockDim.x + threadIdx.x;
    if (t < NTOK) g_present[ids[t]] = 1;
}
__global__ void scanall_k()
{
    __shared__ int ssum[1024];
    int t = threadIdx.x;
    int base = t * 64;
    int s = 0;
    for (int j = 0; j < 64; j++) s += g_present[base + j];
    ssum[t] = s; __syncthreads();
    for (int off = 1; off < 1024; off <<= 1) {
        int v = (t >= off) ? ssum[t - off] : 0;
        __syncthreads();
        ssum[t] += v;
        __syncthreads();
    }
    int run = ssum[t] - s;
    if (t == 1023) g_ucnt[0] = ssum[t];
    for (int j = 0; j < 64; j++) {
        int g = base + j;
        int p = g_present[g];
        g_cidx[g] = run;
        if (p) g_ulist[run] = g;
        run += p;
    }
}
__global__ void tokc_k(const int* __restrict__ ids)
{
    int t = blockIdx.x * blockDim.x + threadIdx.x;
    if (t < NTOK) g_tokc[t] = g_cidx[ids[t]];
}

// ---------------------------------------------------------------------------
// BF16 3-product split GEMM (h*h + l*h + h*l), fp32 accumulate.
// Block 128x256, BK=32, 512 threads (16 warps, 4m x 4n, warp tile 32x64).
// A smem [128][40] bf16 (hi+lo planes), B smem [256][40] bf16, double buffer.
// Fragments via ldmatrix.x4; B planes are pre-transposed [N][K] in gmem.
// Fixed k-ascending accumulation => deterministic per gathered row.
// ---------------------------------------------------------------------------
#define A_STRB 40
#define A_PL   (128*A_STRB)                 // 5120 bf16
#define B_PL   (256*A_STRB)                 // 10240 bf16
#define BUF_E  (2*A_PL + 2*B_PL)            // 30720 bf16
#define BUF_B  (BUF_E*2)                    // 61440 bytes
#define GEMM_SMEM (2*BUF_B)                 // 122880 bytes

__global__ void __launch_bounds__(512, 1) gemm_bf(
    const float* __restrict__ Araw,                    // non-null -> gathered fp32 A
    const bf16* __restrict__ AhG, const bf16* __restrict__ AlG,
    const bf16* __restrict__ Bh0, const bf16* __restrict__ Bl0,
    float* __restrict__ C0, const float* __restrict__ bias0,
    const bf16* __restrict__ Bh1, const bf16* __restrict__ Bl1,
    float* __restrict__ C1, const float* __restrict__ bias1,
    int Kdim, int Ndim,
    const int* __restrict__ gather,
    int act,                                           // 0=none 1=relu
    const int* __restrict__ ucntp,
    int dual,
    bf16* __restrict__ Ch, bf16* __restrict__ Cl)      // optional split out
{
    extern __shared__ bf16 smbf[];
    const int bm = blockIdx.x * 128;
    if (bm >= ucntp[0]) return;

    const bf16 *BhG, *BlG;
    const float* bias_;
    float* Cp;
    int bn;
    if (dual && blockIdx.y) { BhG = Bh1; BlG = Bl1; Cp = C1; bias_ = bias1; bn = 0; }
    else { BhG = Bh0; BlG = Bl0; Cp = C0; bias_ = bias0; bn = dual ? 0 : blockIdx.y * 256; }

    const int tid = threadIdx.x;
    const int wid = tid >> 5, lane = tid & 31;
    const int wm = (wid >> 2) * 32, wn = (wid & 3) * 64;
    const int grp = lane >> 2, qd = lane & 3;

    // fill mapping
    const int fa_row = tid >> 2, fa_q = tid & 3;       // A: 128 rows x 4 chunks
    const int fb_row = tid >> 1, fb_h = tid & 1;       // B: 256 rows x 2 chunk-pairs

    int ar = bm + fa_row;
    if (gather) ar = gather[ar];
    const bool gatherA = (Araw != nullptr);
    const float* ApR = gatherA ? (Araw + (size_t)ar * Kdim + fa_q * 8) : nullptr;
    const bf16* AhR = gatherA ? nullptr : (AhG + (size_t)(bm + fa_row) * Kdim + fa_q * 8);
    const bf16* AlR = gatherA ? nullptr : (AlG + (size_t)(bm + fa_row) * Kdim + fa_q * 8);
    const bf16* BhR = BhG + (size_t)(bn + fb_row) * Kdim;
    const bf16* BlR = BlG + (size_t)(bn + fb_row) * Kdim;

    float acc[2][8][4];
#pragma unroll
    for (int mi = 0; mi < 2; mi++)
#pragma unroll
        for (int ni = 0; ni < 8; ni++)
#pragma unroll
            for (int j = 0; j < 4; j++) acc[mi][ni][j] = 0.f;

    const int ktiles = Kdim >> 5;

    // smem plane byte offsets within a buffer
    const uint32_t smBase = s2u(smbf);
    // fragment load base addresses (byte offsets; add buffer offset per iter)
    const uint32_t aFrag = (uint32_t)((wm + (lane & 15)) * (A_STRB*2)) + ((lane >> 4) * 16);
    const uint32_t bFrag = (uint32_t)(2*A_PL*2) +
        (uint32_t)((wn + (lane & 7) + ((lane >> 4) & 1) * 8) * (A_STRB*2)) +
        (((lane >> 3) & 1) * 16);

    auto issueB = [&](int bufo, int kt) {
        uint32_t dh = smBase + bufo + 2*A_PL*2 + (fb_row*A_STRB + fb_h*16) * 2;
        uint32_t dl = dh + B_PL*2;
        const bf16* sh = BhR + kt*32 + fb_h*16;
        const bf16* sl = BlR + kt*32 + fb_h*16;
        cpasync16(dh,      sh);
        cpasync16(dh + 16, sh + 8);
        cpasync16(dl,      sl);
        cpasync16(dl + 16, sl + 8);
    };
    auto issueA = [&](int bufo, int kt) {
        uint32_t dh = smBase + bufo + (fa_row*A_STRB + fa_q*8) * 2;
        cpasync16(dh,            AhR + kt*32);
        cpasync16(dh + A_PL*2,   AlR + kt*32);
    };
    auto stageAgather = [&](int bufo, int kt) {
        float4 v0 = *(const float4*)(ApR + kt*32);
        float4 v1 = *(const float4*)(ApR + kt*32 + 4);
        bf16 h[8], l[8];
        split_bf(v0.x, h[0], l[0]); split_bf(v0.y, h[1], l[1]);
        split_bf(v0.z, h[2], l[2]); split_bf(v0.w, h[3], l[3]);
        split_bf(v1.x, h[4], l[4]); split_bf(v1.y, h[5], l[5]);
        split_bf(v1.z, h[6], l[6]); split_bf(v1.w, h[7], l[7]);
        uint32_t off = bufo + (fa_row*A_STRB + fa_q*8) * 2;
        uint4 ph = make_uint4(pack2(h[0],h[1]), pack2(h[2],h[3]),
                              pack2(h[4],h[5]), pack2(h[6],h[7]));
        uint4 pl = make_uint4(pack2(l[0],l[1]), pack2(l[2],l[3]),
                              pack2(l[4],l[5]), pack2(l[6],l[7]));
        *(uint4*)((char*)smbf + off)           = ph;
        *(uint4*)((char*)smbf + off + A_PL*2)  = pl;
    };

    // prologue
    if (gatherA) stageAgather(0, 0); else issueA(0, 0);
    issueB(0, 0);
    CP_COMMIT(); CP_WAIT0();
    __syncthreads();

    for (int kt = 0; kt < ktiles; kt++) {
        const int curo = (kt & 1) * BUF_B;
        const int nxto = curo ^ BUF_B;
        const bool more = (kt + 1 < ktiles);
        if (more) {
            issueB(nxto, kt + 1);
            if (gatherA) stageAgather(nxto, kt + 1); else issueA(nxto, kt + 1);
            CP_COMMIT();
        }

#pragma unroll
        for (int k16 = 0; k16 < 2; k16++) {
            uint32_t aH[2][4], aL[2][4];
#pragma unroll
            for (int mi = 0; mi < 2; mi++) {
                uint32_t addr = smBase + curo + aFrag + mi*16*(A_STRB*2) + k16*32;
                ldsm_x4(aH[mi], addr);
                ldsm_x4(aL[mi], addr + A_PL*2);
            }
#pragma unroll
            for (int nig = 0; nig < 4; nig++) {
                uint32_t bH[4], bL[4];
                uint32_t addr = smBase + curo + bFrag + nig*16*(A_STRB*2) + k16*32;
                ldsm_x4(bH, addr);
                ldsm_x4(bL, addr + B_PL*2);
#pragma unroll
                for (int s = 0; s < 2; s++) {
                    const int ni = nig*2 + s;
#pragma unroll
                    for (int mi = 0; mi < 2; mi++) {
                        mma_bf16(acc[mi][ni], aH[mi], bH[2*s], bH[2*s+1]);
                        mma_bf16(acc[mi][ni], aL[mi], bH[2*s], bH[2*s+1]);
                        mma_bf16(acc[mi][ni], aH[mi], bL[2*s], bL[2*s+1]);
                    }
                }
            }
        }

        if (more) CP_WAIT0();
        __syncthreads();
    }

    // epilogue
#pragma unroll
    for (int mi = 0; mi < 2; mi++) {
        const int r0 = bm + wm + mi*16 + grp;
#pragma unroll
        for (int ni = 0; ni < 8; ni++) {
            const int n = bn + wn + ni*8 + qd*2;
            float b0 = bias_ ? bias_[n]   : 0.f;
            float b1 = bias_ ? bias_[n+1] : 0.f;
            float v0 = acc[mi][ni][0] + b0, v1 = acc[mi][ni][1] + b1;
            float v2 = acc[mi][ni][2] + b0, v3 = acc[mi][ni][3] + b1;
            if (act == 1) {
                v0 = fmaxf(v0, 0.f); v1 = fmaxf(v1, 0.f);
                v2 = fmaxf(v2, 0.f); v3 = fmaxf(v3, 0.f);
            }
            if (Cp) {
                *(float2*)&Cp[(size_t)r0 * Ndim + n]     = make_float2(v0, v1);
                *(float2*)&Cp[(size_t)(r0+8) * Ndim + n] = make_float2(v2, v3);
            }
            if (Ch) {
                bf16 h0,l0,h1,l1,h2,l2,h3,l3;
                split_bf(v0,h0,l0); split_bf(v1,h1,l1);
                split_bf(v2,h2,l2); split_bf(v3,h3,l3);
                *(uint32_t*)&Ch[(size_t)r0 * Ndim + n]     = pack2(h0, h1);
                *(uint32_t*)&Ch[(size_t)(r0+8) * Ndim + n] = pack2(h2, h3);
                *(uint32_t*)&Cl[(size_t)r0 * Ndim + n]     = pack2(l0, l1);
                *(uint32_t*)&Cl[(size_t)(r0+8) * Ndim + n] = pack2(l2, l3);
            }
        }
    }
}

// ---------------------------------------------------------------------------
// LayerNorm: one warp per unique row; writes raw VT + bf16 split planes.
// ---------------------------------------------------------------------------
__global__ void ln_k2(const float* __restrict__ gamma, const float* __restrict__ beta,
                      const int* __restrict__ ucntp)
{
    int row  = blockIdx.x * 8 + (threadIdx.x >> 5);
    int lane = threadIdx.x & 31;
    if (row >= ucntp[0]) return;
    const float4* y4 = (const float4*)(g_Y + (size_t)row * DM);
    float4 v0 = y4[lane], v1 = y4[lane + 32];
    float s = v0.x+v0.y+v0.z+v0.w + v1.x+v1.y+v1.z+v1.w;
    for (int o = 16; o > 0; o >>= 1) s += __shfl_xor_sync(0xffffffffu, s, o);
    float mu = s * (1.f/DM);
    float4 c0 = make_float4(v0.x-mu, v0.y-mu, v0.z-mu, v0.w-mu);
    float4 c1 = make_float4(v1.x-mu, v1.y-mu, v1.z-mu, v1.w-mu);
    float q = c0.x*c0.x+c0.y*c0.y+c0.z*c0.z+c0.w*c0.w
            + c1.x*c1.x+c1.y*c1.y+c1.z*c1.z+c1.w*c1.w;
    for (int o = 16; o > 0; o >>= 1) q += __shfl_xor_sync(0xffffffffu, q, o);
    float is = rsqrtf(q * (1.f/DM) + 1e-5f);
    const float4* g4 = (const float4*)gamma;
    const float4* b4 = (const float4*)beta;
    float4 ga = g4[lane], gb = g4[lane+32], ba = b4[lane], bb = b4[lane+32];
    float4 o0 = make_float4(ga.x*c0.x*is+ba.x, ga.y*c0.y*is+ba.y,
                            ga.z*c0.z*is+ba.z, ga.w*c0.w*is+ba.w);
    float4 o1 = make_float4(gb.x*c1.x*is+bb.x, gb.y*c1.y*is+bb.y,
                            gb.z*c1.z*is+bb.z, gb.w*c1.w*is+bb.w);
    float4* vt4 = (float4*)(g_VT + (size_t)row * DM);
    vt4[lane] = o0; vt4[lane + 32] = o1;
    bf16 h[8], l[8];
    split_bf(o0.x,h[0],l[0]); split_bf(o0.y,h[1],l[1]);
    split_bf(o0.z,h[2],l[2]); split_bf(o0.w,h[3],l[3]);
    split_bf(o1.x,h[4],l[4]); split_bf(o1.y,h[5],l[5]);
    split_bf(o1.z,h[6],l[6]); split_bf(o1.w,h[7],l[7]);
    uint2* vh = (uint2*)(g_VTh + (size_t)row * DM);
    uint2* vl = (uint2*)(g_VTl + (size_t)row * DM);
    vh[lane]      = make_uint2(pack2(h[0],h[1]), pack2(h[2],h[3]));
    vh[lane + 32] = make_uint2(pack2(h[4],h[5]), pack2(h[6],h[7]));
    vl[lane]      = make_uint2(pack2(l[0],l[1]), pack2(l[2],l[3]));
    vl[lane + 32] = make_uint2(pack2(l[4],l[5]), pack2(l[6],l[7]));
}

// ---------------------------------------------------------------------------
// Per-(b,l) precompute
// ---------------------------------------------------------------------------
__global__ void prep_k(const float* __restrict__ v, const float* __restrict__ tv,
                       const float* __restrict__ am_w1, const float* __restrict__ am_b1,
                       const float* __restrict__ wq)
{
    __shared__ float tvs[DM];
    __shared__ float qs[DM];
    int bl = blockIdx.x, d = threadIdx.x;
    float t0 = tv[(size_t)bl*DM + d];
    tvs[d] = t0;
    qs[d]  = t0 + v[(size_t)bl*DM + d];
    __syncthreads();
    float t = am_b1[d], q = 0.f;
    for (int k = 0; k < DM; k++) {
        t = fmaf(tvs[k], am_w1[k*DM + d], t);
        q = fmaf(qs[k],  wq  [k*DM + d], q);
    }
    g_T [(size_t)bl*DM + d] = t;
    g_QW[(size_t)bl*DM + d] = q;
}

// ---------------------------------------------------------------------------
// Per-token score
// ---------------------------------------------------------------------------
__global__ void score2_k(const float* __restrict__ am_w2)
{
    int tok  = blockIdx.x * 8 + (threadIdx.x >> 5);
    int lane = threadIdx.x & 31;
    int c  = g_tokc[tok];
    int bl = tok >> 6;
    const float* s2 = g_S2 + (size_t)c * DM;
    const float* tt = g_T  + (size_t)bl * DM;
    float s = 0.f;
#pragma unroll
    for (int d = lane; d < DM; d += 32)
        s = fmaf(tanhf(s2[d] + tt[d]), am_w2[d], s);
    for (int o = 16; o > 0; o >>= 1) s += __shfl_down_sync(0xffffffffu, s, o);
    if (lane == 0) g_S[tok] = s;
}

// ---------------------------------------------------------------------------
// Per-visit stable sort (softmax->mask->top_k(64 of 64) equivalent)
// ---------------------------------------------------------------------------
__global__ void select_k(const int* __restrict__ masks)
{
    int bl = blockIdx.x, j = threadIdx.x;
    __shared__ float key[64];
    int tok = bl*64 + j;
    float k_ = masks[tok] ? g_S[tok] : neg_inf();
    key[j] = k_; __syncthreads();
    int rank = 0;
    for (int m = 0; m < 64; m++) {
        float o = key[m];
        rank += (o > k_) || (o == k_ && m < j);
    }
    g_selslot[bl*64 + rank] = (bl % LSEQ) * NBLK + j;
}

// ---------------------------------------------------------------------------
// Sequential memory recurrence
// ---------------------------------------------------------------------------
__global__ void recur_k(const int* __restrict__ ids, const int* __restrict__ masks,
                        const int* __restrict__ lens)
{
    int b = blockIdx.x, tid = threadIdx.x;
    __shared__ __align__(16) float qw[DM];
    __shared__ int cslot[64], cmask[64];
    __shared__ int nslot[64], nmask[64];
    __shared__ int dslot[128], dmask[128], dcid[128];
    __shared__ float ev[128];

    if (tid < 64) {
        int slot = g_selslot[(b*LSEQ + 0)*64 + tid];
        cslot[tid] = slot;
        cmask[tid] = masks[b*SLOTS + slot];
    }
    int lb = lens[b];
    __syncthreads();

    for (int t = 1; t < LSEQ; t++) {
        qw[tid] = g_QW[(size_t)(b*LSEQ + t)*DM + tid];
        if (tid < 128) {
            int slot = (tid < 64) ? cslot[tid] : g_selslot[(b*LSEQ + t)*64 + (tid - 64)];
            dslot[tid] = slot;
            dmask[tid] = (tid < 64) ? cmask[tid] : masks[b*SLOTS + slot];
            dcid [tid] = g_tokc[b*SLOTS + slot];
        }
        __syncthreads();

        int w = tid >> 5, lane = tid & 31;
        for (int c = w; c < 128; c += 8) {
            const float4* kv = (const float4*)(g_KV + (size_t)dcid[c] * DM);
            const float4* q4 = (const float4*)qw;
            float4 k0 = kv[lane*2], k1 = kv[lane*2 + 1];
            float4 q0 = q4[lane*2], q1 = q4[lane*2 + 1];
            float s = k0.x*q0.x + k0.y*q0.y + k0.z*q0.z + k0.w*q0.w
                    + k1.x*q1.x + k1.y*q1.y + k1.z*q1.z + k1.w*q1.w;
            for (int o = 16; o > 0; o >>= 1) s += __shfl_down_sync(0xffffffffu, s, o);
            if (lane == 0) ev[c] = s;
        }
        __syncthreads();

        if (tid < 128) {
            float k_ = dmask[tid] ? ev[tid] : neg_inf();
            int rank = 0;
            for (int m = 0; m < 128; m++) {
                float o = dmask[m] ? ev[m] : neg_inf();
                rank += (o > k_) || (o == k_ && m < tid);
            }
            if (rank < 64) { nslot[rank] = dslot[tid]; nmask[rank] = dmask[tid]; }
        }
        __syncthreads();
        if (tid < 64) {
            cslot[tid] = nslot[tid];
            cmask[tid] = nmask[tid];
            if (t == lb - 1) g_fslot[b*64 + tid] = nslot[tid];
        }
        __syncthreads();
    }
}

// ---------------------------------------------------------------------------
// Pools
// ---------------------------------------------------------------------------
__global__ void final_k(const float* __restrict__ tv, const int* __restrict__ ids,
                        const int* __restrict__ lens)
{
    int b = blockIdx.x, d = threadIdx.x;
    int lb = lens[b];
    float mx = neg_inf();
    for (int l = 0; l < lb; l++) mx = fmaxf(mx, tv[((size_t)b*LSEQ + l)*DM + d]);
    g_vfin[b*DM + d] = mx;
    float mv = neg_inf();
    for (int m = 0; m < 64; m++) {
        int c = g_tokc[b*SLOTS + g_fslot[b*64 + m]];
        mv = fmaxf(mv, g_VT[(size_t)c*DM + d]);
    }
    g_mfin[b*DM + d] = mv;
    if (d < 64) g_fid[b*64 + d] = ids[b*SLOTS + g_fslot[b*64 + d]];
}

// ---------------------------------------------------------------------------
// Output head + flatten
// ---------------------------------------------------------------------------
__global__ void out_k(const float* __restrict__ ow, const float* __restrict__ ob,
                      float* __restrict__ out, int out_size)
{
    int tid = threadIdx.x;
    if (tid < 32) {
        int b = tid >> 1, o = tid & 1;
        float v = ob[o];
        for (int d = 0; d < DM; d++) v = fmaf(g_vfin[b*DM + d], ow[d*2 + o], v);
        for (int d = 0; d < DM; d++) v = fmaf(g_mfin[b*DM + d], ow[(DM + d)*2 + o], v);
        if (tid < out_size) out[tid] = v;
    }
    for (int i = tid; i < BSZ*64; i += blockDim.x)
        if (32 + i < out_size) out[32 + i] = (float)g_fid[i];
    for (int i = 32 + BSZ*64 + tid; i < out_size; i += blockDim.x)
        out[i] = 0.f;
}

// ---------------------------------------------------------------------------
// Launch
// ---------------------------------------------------------------------------
extern "C" void kernel_launch(void* const* d_in, const int* in_sizes, int n_in,
                              void* d_out, int out_size)
{
    const float* v_all  = (const float*)d_in[0];
    const float* tv_all = (const float*)d_in[1];
    const float* emb    = (const float*)d_in[2];
    const float* w1     = (const float*)d_in[3];
    const float* b1     = (const float*)d_in[4];
    const float* w2     = (const float*)d_in[5];
    const float* b2     = (const float*)d_in[6];
    const float* gam    = (const float*)d_in[7];
    const float* bet    = (const float*)d_in[8];
    const float* wq     = (const float*)d_in[9];
    const float* wk     = (const float*)d_in[10];
    const float* amw1   = (const float*)d_in[11];
    const float* amb1   = (const float*)d_in[12];
    const float* amw2   = (const float*)d_in[13];
    const float* ow     = (const float*)d_in[14];
    const float* ob     = (const float*)d_in[15];
    const int*   itxt   = (const int*)d_in[16];
    const int*   mtxt   = (const int*)d_in[17];
    const int*   lens   = (const int*)d_in[18];
    float* out = (float*)d_out;

    bf16 *pHh, *pHl, *pVTh, *pVTl, *pBh, *pBl;
    float *pY, *pKV, *pS2;
    int *pU, *pUL;
    cudaGetSymbolAddress((void**)&pHh,  g_Hh);
    cudaGetSymbolAddress((void**)&pHl,  g_Hl);
    cudaGetSymbolAddress((void**)&pY,   g_Y);
    cudaGetSymbolAddress((void**)&pVTh, g_VTh);
    cudaGetSymbolAddress((void**)&pVTl, g_VTl);
    cudaGetSymbolAddress((void**)&pKV,  g_KV);
    cudaGetSymbolAddress((void**)&pS2,  g_S2);
    cudaGetSymbolAddress((void**)&pBh,  g_Bh);
    cudaGetSymbolAddress((void**)&pBl,  g_Bl);
    cudaGetSymbolAddress((void**)&pU,   g_ucnt);
    cudaGetSymbolAddress((void**)&pUL,  g_ulist);

    cudaFuncSetAttribute(gemm_bf, cudaFuncAttributeMaxDynamicSharedMemorySize, GEMM_SMEM);

    // 0..2: dedup + weight split (gemm1 at profiled launch index 3)
    zero_split_k<<<512, 256>>>(w1, w2, wk, amw1 + DM*DM);
    mark_k<<<NTOK/256, 256>>>(itxt);
    scanall_k<<<1, 1024>>>();

    // 3: GEMM1: relu(emb[gather] @ w1 + b1) -> bf16 planes g_Hh/g_Hl
    gemm_bf<<<dim3(NVOC/128, 2), 512, GEMM_SMEM>>>(
        emb, nullptr, nullptr,
        pBh + OFF_W1, pBl + OFF_W1, nullptr, b1,
        nullptr, nullptr, nullptr, nullptr,
        KD, DH, pUL, 1, pU, 0, pHh, pHl);

    tokc_k<<<NTOK/256, 256>>>(itxt);
    prep_k<<<NBL, DM>>>(v_all, tv_all, amw1, amb1, wq);

    // GEMM2: Y = Hplanes @ w2 + b2
    gemm_bf<<<dim3(NVOC/128, 1), 512, GEMM_SMEM>>>(
        nullptr, pHh, pHl,
        pBh + OFF_W2, pBl + OFF_W2, pY, b2,
        nullptr, nullptr, nullptr, nullptr,
        DH, DM, nullptr, 0, pU, 0, nullptr, nullptr);

    ln_k2<<<NVOC/8, 256>>>(gam, bet, pU);

    // GEMM3+4 fused: KV = VT @ wk ; S2 = VT @ am_w1[D:]
    gemm_bf<<<dim3(NVOC/128, 2), 512, GEMM_SMEM>>>(
        nullptr, pVTh, pVTl,
        pBh + OFF_WK, pBl + OFF_WK, pKV, nullptr,
        pBh + OFF_AM, pBl + OFF_AM, pS2, nullptr,
        DM, DM, nullptr, 0, pU, 1, nullptr, nullptr);

    // score + selection + recurrence + pooling + head
    score2_k<<<NTOK/8, 256>>>(amw2);
    select_k<<<NBL, 64>>>(mtxt);
    recur_k<<<BSZ, 256>>>(itxt, mtxt, lens);
    final_k<<<BSZ, DM>>>(tv_all, itxt, lens);
    out_k<<<1, 256>>>(ow, ob, out, out_size);
}

// round 10
// speedup vs baseline: 1.3626x; 1.0070x over previous
#include <cuda_runtime.h>
#include <cuda_bf16.h>
#include <math.h>
#include <stdint.h>

// ---------------------------------------------------------------------------
// Problem constants
// ---------------------------------------------------------------------------
#define BSZ   16
#define LSEQ  50
#define NBLK  64
#define DM    256
#define DH    512
#define KD    768
#define NVOC  65536
#define NTOK  (BSZ*LSEQ*NBLK)   // 51200
#define NBL   (BSZ*LSEQ)        // 800
#define SLOTS (LSEQ*NBLK)       // 3200 per batch

typedef __nv_bfloat16 bf16;

__device__ __forceinline__ float neg_inf() { return __int_as_float(0xff800000); }

// ---------------------------------------------------------------------------
// Scratch (static device globals; no allocation)
// ---------------------------------------------------------------------------
__device__ __align__(128) bf16  g_Hh[(size_t)NVOC*DH];  // relu hidden, bf16-hi
__device__ __align__(128) bf16  g_Hl[(size_t)NVOC*DH];  // relu hidden, bf16-lo
__device__ __align__(128) float g_Y [(size_t)NVOC*DM];  // pre-LN
__device__ __align__(128) float g_VT [(size_t)NVOC*DM]; // v_text post-LN (raw)
__device__ __align__(128) bf16  g_VTh[(size_t)NVOC*DM]; // v_text hi
__device__ __align__(128) bf16  g_VTl[(size_t)NVOC*DM]; // v_text lo
__device__ __align__(128) float g_KV[(size_t)NVOC*DM];  // v_text @ wk
__device__ __align__(128) float g_S2[(size_t)NVOC*DM];  // v_text @ am_w1[D:]
__device__ __align__(128) float g_S [NTOK];
__device__ __align__(128) float g_T [NBL*DM];
__device__ __align__(128) float g_QW[NBL*DM];

// pre-split TRANSPOSED weight planes ([N][K], k-contiguous): w1 | w2 | wk | am
#define OFF_W1 0
#define OFF_W2 393216
#define OFF_WK 524288
#define OFF_AM 589824
#define TOTW   655360
__device__ __align__(128) bf16 g_Bh[TOTW];
__device__ __align__(128) bf16 g_Bl[TOTW];

__device__ int   g_present[NVOC];
__device__ int   g_cidx[NVOC];
__device__ int   g_ulist[NVOC];
__device__ int   g_ucnt[1];
__device__ int   g_tokc[NTOK];
__device__ int   g_selslot[NTOK];
__device__ int   g_fslot[BSZ*64];
__device__ int   g_fid  [BSZ*64];
__device__ __align__(128) float g_vfin[BSZ*DM];
__device__ __align__(128) float g_mfin[BSZ*DM];

// ---------------------------------------------------------------------------
// helpers
// ---------------------------------------------------------------------------
__device__ __forceinline__ void split_bf(float x, bf16& h, bf16& l)
{
    h = __float2bfloat16_rn(x);
    l = __float2bfloat16_rn(x - __bfloat162float(h));
}
__device__ __forceinline__ uint32_t pack2(bf16 a, bf16 b)
{
    return (uint32_t)__bfloat16_as_ushort(a) | ((uint32_t)__bfloat16_as_ushort(b) << 16);
}
__device__ __forceinline__ void mma_bf16(float c[4], const uint32_t a[4],
                                         uint32_t b0, uint32_t b1)
{
    asm volatile(
        "mma.sync.aligned.m16n8k16.row.col.f32.bf16.bf16.f32 "
        "{%0,%1,%2,%3}, {%4,%5,%6,%7}, {%8,%9}, {%0,%1,%2,%3};"
        : "+f"(c[0]), "+f"(c[1]), "+f"(c[2]), "+f"(c[3])
        : "r"(a[0]), "r"(a[1]), "r"(a[2]), "r"(a[3]), "r"(b0), "r"(b1));
}
__device__ __forceinline__ void ldsm_x4(uint32_t r[4], uint32_t saddr)
{
    asm volatile("ldmatrix.sync.aligned.m8n8.x4.shared.b16 {%0,%1,%2,%3}, [%4];"
        : "=r"(r[0]), "=r"(r[1]), "=r"(r[2]), "=r"(r[3]) : "r"(saddr));
}
__device__ __forceinline__ uint32_t s2u(const void* p)
{
    return (uint32_t)__cvta_generic_to_shared(p);
}
__device__ __forceinline__ void cpasync16(uint32_t dst, const void* src)
{
    asm volatile("cp.async.ca.shared.global [%0], [%1], 16;" :: "r"(dst), "l"(src));
}
#define CP_COMMIT() asm volatile("cp.async.commit_group;")
#define CP_WAIT0()  asm volatile("cp.async.wait_group 0;")

// ---------------------------------------------------------------------------
// Launch 0: zero present/ulist + tiled transpose-split of all weights
// ([K][N] fp32 -> [N][K] bf16 hi/lo planes). 640 blocks x 256 thr.
// ---------------------------------------------------------------------------
__global__ void prep0_k(const float* __restrict__ w1, const float* __restrict__ w2,
                        const float* __restrict__ wk, const float* __restrict__ am1)
{
    int bid = blockIdx.x, tid = threadIdx.x;
    if (bid < 256) g_present[bid*256 + tid] = 0;
    else if (bid < 512) g_ulist[(bid-256)*256 + tid] = 0;

    const float* W; bf16 *oh, *ol; int K, N, kt, nt;
    int id = bid;
    if (id < 384)      { W = w1;  oh = g_Bh+OFF_W1; ol = g_Bl+OFF_W1; K = KD; N = DH; kt = id % 24; nt = id / 24; }
    else if (id < 512) { id -= 384; W = w2;  oh = g_Bh+OFF_W2; ol = g_Bl+OFF_W2; K = DH; N = DM; kt = id % 16; nt = id / 16; }
    else if (id < 576) { id -= 512; W = wk;  oh = g_Bh+OFF_WK; ol = g_Bl+OFF_WK; K = DM; N = DM; kt = id % 8;  nt = id / 8; }
    else               { id -= 576; W = am1; oh = g_Bh+OFF_AM; ol = g_Bl+OFF_AM; K = DM; N = DM; kt = id % 8;  nt = id / 8; }

    __shared__ float t[32][33];
    int tx = tid & 31, ty = tid >> 5;
#pragma unroll
    for (int i = 0; i < 4; i++) {
        int k = kt*32 + ty + i*8, n = nt*32 + tx;
        t[ty + i*8][tx] = W[(size_t)k*N + n];
    }
    __syncthreads();
#pragma unroll
    for (int i = 0; i < 4; i++) {
        int n = nt*32 + ty + i*8, k = kt*32 + tx;
        split_bf(t[tx][ty + i*8], oh[(size_t)n*K + k], ol[(size_t)n*K + k]);
    }
}
__global__ void mark_k(const int* __restrict__ ids)
{
    int t = blockIdx.x * blockDim.x + threadIdx.x;
    if (t < NTOK) g_present[ids[t]] = 1;
}
__global__ void scanall_k()
{
    __shared__ int ssum[1024];
    int t = threadIdx.x;
    int base = t * 64;
    int s = 0;
    for (int j = 0; j < 64; j++) s += g_present[base + j];
    ssum[t] = s; __syncthreads();
    for (int off = 1; off < 1024; off <<= 1) {
        int v = (t >= off) ? ssum[t - off] : 0;
        __syncthreads();
        ssum[t] += v;
        __syncthreads();
    }
    int run = ssum[t] - s;
    if (t == 1023) g_ucnt[0] = ssum[t];
    for (int j = 0; j < 64; j++) {
        int g = base + j;
        int p = g_present[g];
        g_cidx[g] = run;
        if (p) g_ulist[run] = g;
        run += p;
    }
}
__global__ void tokc_k(const int* __restrict__ ids)
{
    int t = blockIdx.x * blockDim.x + threadIdx.x;
    if (t < NTOK) g_tokc[t] = g_cidx[ids[t]];
}

// ---------------------------------------------------------------------------
// BF16 3-product split GEMM (h*h + l*h + h*l), fp32 accumulate.
// Block 128x256, BK=32, 512 threads (16 warps, 4m x 4n, warp tile 32x64).
// Round-6-proven 2-stage double buffer; ldmatrix.x4 fragments; pass-major
// MMA order so same-accumulator reuse distance is 4 (no HMMA RAW stalls).
// Per-element accumulation order (hh, lh, hl per k16, k ascending) is fixed
// => deterministic per gathered row => duplicate-id ties bitwise exact.
// ---------------------------------------------------------------------------
#define A_STRB 40
#define A_PL   (128*A_STRB)                 // 5120 bf16
#define B_PL   (256*A_STRB)                 // 10240 bf16
#define BUF_E  (2*A_PL + 2*B_PL)            // 30720 bf16
#define BUF_B  (BUF_E*2)                    // 61440 bytes
#define GEMM_SMEM (2*BUF_B)                 // 122880 bytes

__global__ void __launch_bounds__(512, 1) gemm_bf(
    const float* __restrict__ Araw,                    // non-null -> gathered fp32 A
    const bf16* __restrict__ AhG, const bf16* __restrict__ AlG,
    const bf16* __restrict__ Bh0, const bf16* __restrict__ Bl0,
    float* __restrict__ C0, const float* __restrict__ bias0,
    const bf16* __restrict__ Bh1, const bf16* __restrict__ Bl1,
    float* __restrict__ C1, const float* __restrict__ bias1,
    int Kdim, int Ndim,
    const int* __restrict__ gather,
    int act,                                           // 0=none 1=relu
    const int* __restrict__ ucntp,
    int dual,
    bf16* __restrict__ Ch, bf16* __restrict__ Cl)      // optional split out
{
    extern __shared__ bf16 smbf[];
    const int bm = blockIdx.x * 128;
    if (bm >= ucntp[0]) return;

    const bf16 *BhG, *BlG;
    const float* bias_;
    float* Cp;
    int bn;
    if (dual && blockIdx.y) { BhG = Bh1; BlG = Bl1; Cp = C1; bias_ = bias1; bn = 0; }
    else { BhG = Bh0; BlG = Bl0; Cp = C0; bias_ = bias0; bn = dual ? 0 : blockIdx.y * 256; }

    const int tid = threadIdx.x;
    const int wid = tid >> 5, lane = tid & 31;
    const int wm = (wid >> 2) * 32, wn = (wid & 3) * 64;
    const int grp = lane >> 2, qd = lane & 3;

    // fill mapping
    const int fa_row = tid >> 2, fa_q = tid & 3;       // A: 128 rows x 4 chunks
    const int fb_row = tid >> 1, fb_h = tid & 1;       // B: 256 rows x 2 chunk-pairs

    int ar = bm + fa_row;
    if (gather) ar = gather[ar];
    const bool gatherA = (Araw != nullptr);
    const float* ApR = gatherA ? (Araw + (size_t)ar * Kdim + fa_q * 8) : nullptr;
    const bf16* AhR = gatherA ? nullptr : (AhG + (size_t)(bm + fa_row) * Kdim + fa_q * 8);
    const bf16* AlR = gatherA ? nullptr : (AlG + (size_t)(bm + fa_row) * Kdim + fa_q * 8);
    const bf16* BhR = BhG + (size_t)(bn + fb_row) * Kdim;
    const bf16* BlR = BlG + (size_t)(bn + fb_row) * Kdim;

    float acc[2][8][4];
#pragma unroll
    for (int mi = 0; mi < 2; mi++)
#pragma unroll
        for (int ni = 0; ni < 8; ni++)
#pragma unroll
            for (int j = 0; j < 4; j++) acc[mi][ni][j] = 0.f;

    const int ktiles = Kdim >> 5;

    const uint32_t smBase = s2u(smbf);
    const uint32_t aFrag = (uint32_t)((wm + (lane & 15)) * (A_STRB*2)) + ((lane >> 4) * 16);
    const uint32_t bFrag = (uint32_t)(2*A_PL*2) +
        (uint32_t)((wn + (lane & 7) + ((lane >> 4) & 1) * 8) * (A_STRB*2)) +
        (((lane >> 3) & 1) * 16);

    auto issueB = [&](int bufo, int kt) {
        uint32_t dh = smBase + bufo + 2*A_PL*2 + (fb_row*A_STRB + fb_h*16) * 2;
        uint32_t dl = dh + B_PL*2;
        const bf16* sh = BhR + kt*32 + fb_h*16;
        const bf16* sl = BlR + kt*32 + fb_h*16;
        cpasync16(dh,      sh);
        cpasync16(dh + 16, sh + 8);
        cpasync16(dl,      sl);
        cpasync16(dl + 16, sl + 8);
    };
    auto issueA = [&](int bufo, int kt) {
        uint32_t dh = smBase + bufo + (fa_row*A_STRB + fa_q*8) * 2;
        cpasync16(dh,            AhR + kt*32);
        cpasync16(dh + A_PL*2,   AlR + kt*32);
    };
    auto stageAgather = [&](int bufo, int kt) {
        float4 v0 = *(const float4*)(ApR + kt*32);
        float4 v1 = *(const float4*)(ApR + kt*32 + 4);
        bf16 h[8], l[8];
        split_bf(v0.x, h[0], l[0]); split_bf(v0.y, h[1], l[1]);
        split_bf(v0.z, h[2], l[2]); split_bf(v0.w, h[3], l[3]);
        split_bf(v1.x, h[4], l[4]); split_bf(v1.y, h[5], l[5]);
        split_bf(v1.z, h[6], l[6]); split_bf(v1.w, h[7], l[7]);
        uint32_t off = bufo + (fa_row*A_STRB + fa_q*8) * 2;
        uint4 ph = make_uint4(pack2(h[0],h[1]), pack2(h[2],h[3]),
                              pack2(h[4],h[5]), pack2(h[6],h[7]));
        uint4 pl = make_uint4(pack2(l[0],l[1]), pack2(l[2],l[3]),
                              pack2(l[4],l[5]), pack2(l[6],l[7]));
        *(uint4*)((char*)smbf + off)           = ph;
        *(uint4*)((char*)smbf + off + A_PL*2)  = pl;
    };

    // prologue: stage 0 -> buffer 0
    issueB(0, 0);
    if (gatherA) stageAgather(0, 0); else issueA(0, 0);
    CP_COMMIT(); CP_WAIT0();
    __syncthreads();

    for (int kt = 0; kt < ktiles; kt++) {
        const int curo = (kt & 1) * BUF_B;
        const int nxto = curo ^ BUF_B;
        const bool more = (kt + 1 < ktiles);
        if (more) {
            issueB(nxto, kt + 1);
            if (gatherA) stageAgather(nxto, kt + 1); else issueA(nxto, kt + 1);
            CP_COMMIT();
        }

#pragma unroll
        for (int k16 = 0; k16 < 2; k16++) {
            uint32_t aH[2][4], aL[2][4];
#pragma unroll
            for (int mi = 0; mi < 2; mi++) {
                uint32_t addr = smBase + curo + aFrag + mi*16*(A_STRB*2) + k16*32;
                ldsm_x4(aH[mi], addr);
                ldsm_x4(aL[mi], addr + A_PL*2);
            }
#pragma unroll
            for (int nig = 0; nig < 4; nig++) {
                uint32_t bH[4], bL[4];
                uint32_t addr = smBase + curo + bFrag + nig*16*(A_STRB*2) + k16*32;
                ldsm_x4(bH, addr);
                ldsm_x4(bL, addr + B_PL*2);
                // pass-major: same-acc reuse distance 4 (no HMMA RAW stalls);
                // per-element order stays hh, lh, hl within each k16.
#pragma unroll
                for (int s = 0; s < 2; s++)
#pragma unroll
                    for (int mi = 0; mi < 2; mi++)
                        mma_bf16(acc[mi][nig*2+s], aH[mi], bH[2*s], bH[2*s+1]);
#pragma unroll
                for (int s = 0; s < 2; s++)
#pragma unroll
                    for (int mi = 0; mi < 2; mi++)
                        mma_bf16(acc[mi][nig*2+s], aL[mi], bH[2*s], bH[2*s+1]);
#pragma unroll
                for (int s = 0; s < 2; s++)
#pragma unroll
                    for (int mi = 0; mi < 2; mi++)
                        mma_bf16(acc[mi][nig*2+s], aH[mi], bL[2*s], bL[2*s+1]);
            }
        }

        if (more) CP_WAIT0();
        __syncthreads();
    }

    // epilogue
#pragma unroll
    for (int mi = 0; mi < 2; mi++) {
        const int r0 = bm + wm + mi*16 + grp;
#pragma unroll
        for (int ni = 0; ni < 8; ni++) {
            const int n = bn + wn + ni*8 + qd*2;
            float b0 = bias_ ? bias_[n]   : 0.f;
            float b1 = bias_ ? bias_[n+1] : 0.f;
            float v0 = acc[mi][ni][0] + b0, v1 = acc[mi][ni][1] + b1;
            float v2 = acc[mi][ni][2] + b0, v3 = acc[mi][ni][3] + b1;
            if (act == 1) {
                v0 = fmaxf(v0, 0.f); v1 = fmaxf(v1, 0.f);
                v2 = fmaxf(v2, 0.f); v3 = fmaxf(v3, 0.f);
            }
            if (Cp) {
                *(float2*)&Cp[(size_t)r0 * Ndim + n]     = make_float2(v0, v1);
                *(float2*)&Cp[(size_t)(r0+8) * Ndim + n] = make_float2(v2, v3);
            }
            if (Ch) {
                bf16 h0,l0,h1,l1,h2,l2,h3,l3;
                split_bf(v0,h0,l0); split_bf(v1,h1,l1);
                split_bf(v2,h2,l2); split_bf(v3,h3,l3);
                *(uint32_t*)&Ch[(size_t)r0 * Ndim + n]     = pack2(h0, h1);
                *(uint32_t*)&Ch[(size_t)(r0+8) * Ndim + n] = pack2(h2, h3);
                *(uint32_t*)&Cl[(size_t)r0 * Ndim + n]     = pack2(l0, l1);
                *(uint32_t*)&Cl[(size_t)(r0+8) * Ndim + n] = pack2(l2, l3);
            }
        }
    }
}

// ---------------------------------------------------------------------------
// LayerNorm: one warp per unique row; writes raw VT + bf16 split planes.
// ---------------------------------------------------------------------------
__global__ void ln_k2(const float* __restrict__ gamma, const float* __restrict__ beta,
                      const int* __restrict__ ucntp)
{
    int row  = blockIdx.x * 8 + (threadIdx.x >> 5);
    int lane = threadIdx.x & 31;
    if (row >= ucntp[0]) return;
    const float4* y4 = (const float4*)(g_Y + (size_t)row * DM);
    float4 v0 = y4[lane], v1 = y4[lane + 32];
    float s = v0.x+v0.y+v0.z+v0.w + v1.x+v1.y+v1.z+v1.w;
    for (int o = 16; o > 0; o >>= 1) s += __shfl_xor_sync(0xffffffffu, s, o);
    float mu = s * (1.f/DM);
    float4 c0 = make_float4(v0.x-mu, v0.y-mu, v0.z-mu, v0.w-mu);
    float4 c1 = make_float4(v1.x-mu, v1.y-mu, v1.z-mu, v1.w-mu);
    float q = c0.x*c0.x+c0.y*c0.y+c0.z*c0.z+c0.w*c0.w
            + c1.x*c1.x+c1.y*c1.y+c1.z*c1.z+c1.w*c1.w;
    for (int o = 16; o > 0; o >>= 1) q += __shfl_xor_sync(0xffffffffu, q, o);
    float is = rsqrtf(q * (1.f/DM) + 1e-5f);
    const float4* g4 = (const float4*)gamma;
    const float4* b4 = (const float4*)beta;
    float4 ga = g4[lane], gb = g4[lane+32], ba = b4[lane], bb = b4[lane+32];
    float4 o0 = make_float4(ga.x*c0.x*is+ba.x, ga.y*c0.y*is+ba.y,
                            ga.z*c0.z*is+ba.z, ga.w*c0.w*is+ba.w);
    float4 o1 = make_float4(gb.x*c1.x*is+bb.x, gb.y*c1.y*is+bb.y,
                            gb.z*c1.z*is+bb.z, gb.w*c1.w*is+bb.w);
    float4* vt4 = (float4*)(g_VT + (size_t)row * DM);
    vt4[lane] = o0; vt4[lane + 32] = o1;
    bf16 h[8], l[8];
    split_bf(o0.x,h[0],l[0]); split_bf(o0.y,h[1],l[1]);
    split_bf(o0.z,h[2],l[2]); split_bf(o0.w,h[3],l[3]);
    split_bf(o1.x,h[4],l[4]); split_bf(o1.y,h[5],l[5]);
    split_bf(o1.z,h[6],l[6]); split_bf(o1.w,h[7],l[7]);
    uint2* vh = (uint2*)(g_VTh + (size_t)row * DM);
    uint2* vl = (uint2*)(g_VTl + (size_t)row * DM);
    vh[lane]      = make_uint2(pack2(h[0],h[1]), pack2(h[2],h[3]));
    vh[lane + 32] = make_uint2(pack2(h[4],h[5]), pack2(h[6],h[7]));
    vl[lane]      = make_uint2(pack2(l[0],l[1]), pack2(l[2],l[3]));
    vl[lane + 32] = make_uint2(pack2(l[4],l[5]), pack2(l[6],l[7]));
}

// ---------------------------------------------------------------------------
// Per-(b,l) precompute
// ---------------------------------------------------------------------------
__global__ void prep_k(const float* __restrict__ v, const float* __restrict__ tv,
                       const float* __restrict__ am_w1, const float* __restrict__ am_b1,
                       const float* __restrict__ wq)
{
    __shared__ float tvs[DM];
    __shared__ float qs[DM];
    int bl = blockIdx.x, d = threadIdx.x;
    float t0 = tv[(size_t)bl*DM + d];
    tvs[d] = t0;
    qs[d]  = t0 + v[(size_t)bl*DM + d];
    __syncthreads();
    float t = am_b1[d], q = 0.f;
    for (int k = 0; k < DM; k++) {
        t = fmaf(tvs[k], am_w1[k*DM + d], t);
        q = fmaf(qs[k],  wq  [k*DM + d], q);
    }
    g_T [(size_t)bl*DM + d] = t;
    g_QW[(size_t)bl*DM + d] = q;
}

// ---------------------------------------------------------------------------
// Per-token score
// ---------------------------------------------------------------------------
__global__ void score2_k(const float* __restrict__ am_w2)
{
    int tok  = blockIdx.x * 8 + (threadIdx.x >> 5);
    int lane = threadIdx.x & 31;
    int c  = g_tokc[tok];
    int bl = tok >> 6;
    const float* s2 = g_S2 + (size_t)c * DM;
    const float* tt = g_T  + (size_t)bl * DM;
    float s = 0.f;
#pragma unroll
    for (int d = lane; d < DM; d += 32)
        s = fmaf(tanhf(s2[d] + tt[d]), am_w2[d], s);
    for (int o = 16; o > 0; o >>= 1) s += __shfl_down_sync(0xffffffffu, s, o);
    if (lane == 0) g_S[tok] = s;
}

// ---------------------------------------------------------------------------
// Per-visit stable sort (softmax->mask->top_k(64 of 64) equivalent)
// ---------------------------------------------------------------------------
__global__ void select_k(const int* __restrict__ masks)
{
    int bl = blockIdx.x, j = threadIdx.x;
    __shared__ float key[64];
    int tok = bl*64 + j;
    float k_ = masks[tok] ? g_S[tok] : neg_inf();
    key[j] = k_; __syncthreads();
    int rank = 0;
    for (int m = 0; m < 64; m++) {
        float o = key[m];
        rank += (o > k_) || (o == k_ && m < j);
    }
    g_selslot[bl*64 + rank] = (bl % LSEQ) * NBLK + j;
}

// ---------------------------------------------------------------------------
// Sequential memory recurrence
// ---------------------------------------------------------------------------
__global__ void recur_k(const int* __restrict__ ids, const int* __restrict__ masks,
                        const int* __restrict__ lens)
{
    int b = blockIdx.x, tid = threadIdx.x;
    __shared__ __align__(16) float qw[DM];
    __shared__ int cslot[64], cmask[64];
    __shared__ int nslot[64], nmask[64];
    __shared__ int dslot[128], dmask[128], dcid[128];
    __shared__ float ev[128];

    if (tid < 64) {
        int slot = g_selslot[(b*LSEQ + 0)*64 + tid];
        cslot[tid] = slot;
        cmask[tid] = masks[b*SLOTS + slot];
    }
    int lb = lens[b];
    __syncthreads();

    for (int t = 1; t < LSEQ; t++) {
        qw[tid] = g_QW[(size_t)(b*LSEQ + t)*DM + tid];
        if (tid < 128) {
            int slot = (tid < 64) ? cslot[tid] : g_selslot[(b*LSEQ + t)*64 + (tid - 64)];
            dslot[tid] = slot;
            dmask[tid] = (tid < 64) ? cmask[tid] : masks[b*SLOTS + slot];
            dcid [tid] = g_tokc[b*SLOTS + slot];
        }
        __syncthreads();

        int w = tid >> 5, lane = tid & 31;
        for (int c = w; c < 128; c += 8) {
            const float4* kv = (const float4*)(g_KV + (size_t)dcid[c] * DM);
            const float4* q4 = (const float4*)qw;
            float4 k0 = kv[lane*2], k1 = kv[lane*2 + 1];
            float4 q0 = q4[lane*2], q1 = q4[lane*2 + 1];
            float s = k0.x*q0.x + k0.y*q0.y + k0.z*q0.z + k0.w*q0.w
                    + k1.x*q1.x + k1.y*q1.y + k1.z*q1.z + k1.w*q1.w;
            for (int o = 16; o > 0; o >>= 1) s += __shfl_down_sync(0xffffffffu, s, o);
            if (lane == 0) ev[c] = s;
        }
        __syncthreads();

        if (tid < 128) {
            float k_ = dmask[tid] ? ev[tid] : neg_inf();
            int rank = 0;
            for (int m = 0; m < 128; m++) {
                float o = dmask[m] ? ev[m] : neg_inf();
                rank += (o > k_) || (o == k_ && m < tid);
            }
            if (rank < 64) { nslot[rank] = dslot[tid]; nmask[rank] = dmask[tid]; }
        }
        __syncthreads();
        if (tid < 64) {
            cslot[tid] = nslot[tid];
            cmask[tid] = nmask[tid];
            if (t == lb - 1) g_fslot[b*64 + tid] = nslot[tid];
        }
        __syncthreads();
    }
}

// ---------------------------------------------------------------------------
// Pools
// ---------------------------------------------------------------------------
__global__ void final_k(const float* __restrict__ tv, const int* __restrict__ ids,
                        const int* __restrict__ lens)
{
    int b = blockIdx.x, d = threadIdx.x;
    int lb = lens[b];
    float mx = neg_inf();
    for (int l = 0; l < lb; l++) mx = fmaxf(mx, tv[((size_t)b*LSEQ + l)*DM + d]);
    g_vfin[b*DM + d] = mx;
    float mv = neg_inf();
    for (int m = 0; m < 64; m++) {
        int c = g_tokc[b*SLOTS + g_fslot[b*64 + m]];
        mv = fmaxf(mv, g_VT[(size_t)c*DM + d]);
    }
    g_mfin[b*DM + d] = mv;
    if (d < 64) g_fid[b*64 + d] = ids[b*SLOTS + g_fslot[b*64 + d]];
}

// ---------------------------------------------------------------------------
// Output head + flatten
// ---------------------------------------------------------------------------
__global__ void out_k(const float* __restrict__ ow, const float* __restrict__ ob,
                      float* __restrict__ out, int out_size)
{
    int tid = threadIdx.x;
    if (tid < 32) {
        int b = tid >> 1, o = tid & 1;
        float v = ob[o];
        for (int d = 0; d < DM; d++) v = fmaf(g_vfin[b*DM + d], ow[d*2 + o], v);
        for (int d = 0; d < DM; d++) v = fmaf(g_mfin[b*DM + d], ow[(DM + d)*2 + o], v);
        if (tid < out_size) out[tid] = v;
    }
    for (int i = tid; i < BSZ*64; i += blockDim.x)
        if (32 + i < out_size) out[32 + i] = (float)g_fid[i];
    for (int i = 32 + BSZ*64 + tid; i < out_size; i += blockDim.x)
        out[i] = 0.f;
}

// ---------------------------------------------------------------------------
// Launch
// ---------------------------------------------------------------------------
extern "C" void kernel_launch(void* const* d_in, const int* in_sizes, int n_in,
                              void* d_out, int out_size)
{
    const float* v_all  = (const float*)d_in[0];
    const float* tv_all = (const float*)d_in[1];
    const float* emb    = (const float*)d_in[2];
    const float* w1     = (const float*)d_in[3];
    const float* b1     = (const float*)d_in[4];
    const float* w2     = (const float*)d_in[5];
    const float* b2     = (const float*)d_in[6];
    const float* gam    = (const float*)d_in[7];
    const float* bet    = (const float*)d_in[8];
    const float* wq     = (const float*)d_in[9];
    const float* wk     = (const float*)d_in[10];
    const float* amw1   = (const float*)d_in[11];
    const float* amb1   = (const float*)d_in[12];
    const float* amw2   = (const float*)d_in[13];
    const float* ow     = (const float*)d_in[14];
    const float* ob     = (const float*)d_in[15];
    const int*   itxt   = (const int*)d_in[16];
    const int*   mtxt   = (const int*)d_in[17];
    const int*   lens   = (const int*)d_in[18];
    float* out = (float*)d_out;

    bf16 *pHh, *pHl, *pVTh, *pVTl, *pBh, *pBl;
    float *pY, *pKV, *pS2;
    int *pU, *pUL;
    cudaGetSymbolAddress((void**)&pHh,  g_Hh);
    cudaGetSymbolAddress((void**)&pHl,  g_Hl);
    cudaGetSymbolAddress((void**)&pY,   g_Y);
    cudaGetSymbolAddress((void**)&pVTh, g_VTh);
    cudaGetSymbolAddress((void**)&pVTl, g_VTl);
    cudaGetSymbolAddress((void**)&pKV,  g_KV);
    cudaGetSymbolAddress((void**)&pS2,  g_S2);
    cudaGetSymbolAddress((void**)&pBh,  g_Bh);
    cudaGetSymbolAddress((void**)&pBl,  g_Bl);
    cudaGetSymbolAddress((void**)&pU,   g_ucnt);
    cudaGetSymbolAddress((void**)&pUL,  g_ulist);

    cudaFuncSetAttribute(gemm_bf, cudaFuncAttributeMaxDynamicSharedMemorySize, GEMM_SMEM);

    // 0..2: weight transpose+split + dedup (gemm1 at profiled launch index 3)
    prep0_k<<<640, 256>>>(w1, w2, wk, amw1 + DM*DM);
    mark_k<<<NTOK/256, 256>>>(itxt);
    scanall_k<<<1, 1024>>>();

    // 3: GEMM1: relu(emb[gather] @ w1 + b1) -> bf16 planes g_Hh/g_Hl
    gemm_bf<<<dim3(NVOC/128, 2), 512, GEMM_SMEM>>>(
        emb, nullptr, nullptr,
        pBh + OFF_W1, pBl + OFF_W1, nullptr, b1,
        nullptr, nullptr, nullptr, nullptr,
        KD, DH, pUL, 1, pU, 0, pHh, pHl);

    tokc_k<<<NTOK/256, 256>>>(itxt);
    prep_k<<<NBL, DM>>>(v_all, tv_all, amw1, amb1, wq);

    // GEMM2: Y = Hplanes @ w2 + b2
    gemm_bf<<<dim3(NVOC/128, 1), 512, GEMM_SMEM>>>(
        nullptr, pHh, pHl,
        pBh + OFF_W2, pBl + OFF_W2, pY, b2,
        nullptr, nullptr, nullptr, nullptr,
        DH, DM, nullptr, 0, pU, 0, nullptr, nullptr);

    ln_k2<<<NVOC/8, 256>>>(gam, bet, pU);

    // GEMM3+4 fused: KV = VT @ wk ; S2 = VT @ am_w1[D:]
    gemm_bf<<<dim3(NVOC/128, 2), 512, GEMM_SMEM>>>(
        nullptr, pVTh, pVTl,
        pBh + OFF_WK, pBl + OFF_WK, pKV, nullptr,
        pBh + OFF_AM, pBl + OFF_AM, pS2, nullptr,
        DM, DM, nullptr, 0, pU, 1, nullptr, nullptr);

    // score + selection + recurrence + pooling + head
    score2_k<<<NTOK/8, 256>>>(amw2);
    select_k<<<NBL, 64>>>(mtxt);
    recur_k<<<BSZ, 256>>>(itxt, mtxt, lens);
    final_k<<<BSZ, DM>>>(tv_all, itxt, lens);
    out_k<<<1, 256>>>(ow, ob, out, out_size);
}

// round 12
// speedup vs baseline: 1.4756x; 1.0829x over previous
#include <cuda_runtime.h>
#include <cuda_bf16.h>
#include <math.h>
#include <stdint.h>

// ---------------------------------------------------------------------------
// Problem constants
// ---------------------------------------------------------------------------
#define BSZ   16
#define LSEQ  50
#define NBLK  64
#define DM    256
#define DH    512
#define KD    768
#define NVOC  65536
#define NTOK  (BSZ*LSEQ*NBLK)   // 51200
#define NBL   (BSZ*LSEQ)        // 800
#define SLOTS (LSEQ*NBLK)       // 3200 per batch

typedef __nv_bfloat16 bf16;

__device__ __forceinline__ float neg_inf() { return __int_as_float(0xff800000); }

// ---------------------------------------------------------------------------
// Scratch (static device globals; no allocation)
// ---------------------------------------------------------------------------
__device__ __align__(128) bf16  g_Hh[(size_t)NVOC*DH];  // relu hidden, bf16-hi
__device__ __align__(128) bf16  g_Hl[(size_t)NVOC*DH];  // relu hidden, bf16-lo
__device__ __align__(128) bf16  g_VTh[(size_t)NVOC*DM]; // v_text hi (post-LN)
__device__ __align__(128) bf16  g_VTl[(size_t)NVOC*DM]; // v_text lo (post-LN)
__device__ __align__(128) float g_KV[(size_t)NVOC*DM];  // v_text @ wk
__device__ __align__(128) float g_S2[(size_t)NVOC*DM];  // v_text @ am_w1[D:]
__device__ __align__(128) float g_S [NTOK];
__device__ __align__(128) float g_T [NBL*DM];
__device__ __align__(128) float g_QW[NBL*DM];

// pre-split TRANSPOSED weight planes ([N][K], k-contiguous): w1 | w2 | wk | am
#define OFF_W1 0
#define OFF_W2 393216
#define OFF_WK 524288
#define OFF_AM 589824
#define TOTW   655360
__device__ __align__(128) bf16 g_Bh[TOTW];
__device__ __align__(128) bf16 g_Bl[TOTW];

__device__ int   g_present[NVOC];
__device__ int   g_cidx[NVOC];
__device__ int   g_ulist[NVOC];
__device__ int   g_ucnt[1];
__device__ int   g_tokc[NTOK];
__device__ int   g_selslot[NTOK];
__device__ int   g_fslot[BSZ*64];
__device__ int   g_fid  [BSZ*64];
__device__ __align__(128) float g_vfin[BSZ*DM];
__device__ __align__(128) float g_mfin[BSZ*DM];

// ---------------------------------------------------------------------------
// helpers
// ---------------------------------------------------------------------------
__device__ __forceinline__ void split_bf(float x, bf16& h, bf16& l)
{
    h = __float2bfloat16_rn(x);
    l = __float2bfloat16_rn(x - __bfloat162float(h));
}
__device__ __forceinline__ uint32_t pack2(bf16 a, bf16 b)
{
    return (uint32_t)__bfloat16_as_ushort(a) | ((uint32_t)__bfloat16_as_ushort(b) << 16);
}
__device__ __forceinline__ void mma_bf16(float c[4], const uint32_t a[4],
                                         uint32_t b0, uint32_t b1)
{
    asm volatile(
        "mma.sync.aligned.m16n8k16.row.col.f32.bf16.bf16.f32 "
        "{%0,%1,%2,%3}, {%4,%5,%6,%7}, {%8,%9}, {%0,%1,%2,%3};"
        : "+f"(c[0]), "+f"(c[1]), "+f"(c[2]), "+f"(c[3])
        : "r"(a[0]), "r"(a[1]), "r"(a[2]), "r"(a[3]), "r"(b0), "r"(b1));
}
__device__ __forceinline__ void ldsm_x4(uint32_t r[4], uint32_t saddr)
{
    asm volatile("ldmatrix.sync.aligned.m8n8.x4.shared.b16 {%0,%1,%2,%3}, [%4];"
        : "=r"(r[0]), "=r"(r[1]), "=r"(r[2]), "=r"(r[3]) : "r"(saddr));
}
__device__ __forceinline__ uint32_t s2u(const void* p)
{
    return (uint32_t)__cvta_generic_to_shared(p);
}
__device__ __forceinline__ void cpasync16(uint32_t dst, const void* src)
{
    asm volatile("cp.async.ca.shared.global [%0], [%1], 16;" :: "r"(dst), "l"(src));
}
#define CP_COMMIT() asm volatile("cp.async.commit_group;")
#define CP_WAIT0()  asm volatile("cp.async.wait_group 0;")

// ---------------------------------------------------------------------------
// Launch 0: zero present/ulist + tiled transpose-split of all weights
// ([K][N] fp32 -> [N][K] bf16 hi/lo planes). 640 blocks x 256 thr.
// ---------------------------------------------------------------------------
__global__ void prep0_k(const float* __restrict__ w1, const float* __restrict__ w2,
                        const float* __restrict__ wk, const float* __restrict__ am1)
{
    int bid = blockIdx.x, tid = threadIdx.x;
    if (bid < 256) g_present[bid*256 + tid] = 0;
    else if (bid < 512) g_ulist[(bid-256)*256 + tid] = 0;

    const float* W; bf16 *oh, *ol; int K, N, kt, nt;
    int id = bid;
    if (id < 384)      { W = w1;  oh = g_Bh+OFF_W1; ol = g_Bl+OFF_W1; K = KD; N = DH; kt = id % 24; nt = id / 24; }
    else if (id < 512) { id -= 384; W = w2;  oh = g_Bh+OFF_W2; ol = g_Bl+OFF_W2; K = DH; N = DM; kt = id % 16; nt = id / 16; }
    else if (id < 576) { id -= 512; W = wk;  oh = g_Bh+OFF_WK; ol = g_Bl+OFF_WK; K = DM; N = DM; kt = id % 8;  nt = id / 8; }
    else               { id -= 576; W = am1; oh = g_Bh+OFF_AM; ol = g_Bl+OFF_AM; K = DM; N = DM; kt = id % 8;  nt = id / 8; }

    __shared__ float t[32][33];
    int tx = tid & 31, ty = tid >> 5;
#pragma unroll
    for (int i = 0; i < 4; i++) {
        int k = kt*32 + ty + i*8, n = nt*32 + tx;
        t[ty + i*8][tx] = W[(size_t)k*N + n];
    }
    __syncthreads();
#pragma unroll
    for (int i = 0; i < 4; i++) {
        int n = nt*32 + ty + i*8, k = kt*32 + tx;
        split_bf(t[tx][ty + i*8], oh[(size_t)n*K + k], ol[(size_t)n*K + k]);
    }
}
__global__ void mark_k(const int* __restrict__ ids)
{
    int t = blockIdx.x * blockDim.x + threadIdx.x;
    if (t < NTOK) g_present[ids[t]] = 1;
}
__global__ void scanall_k()
{
    __shared__ int ssum[1024];
    int t = threadIdx.x;
    int base = t * 64;
    int s = 0;
    for (int j = 0; j < 64; j++) s += g_present[base + j];
    ssum[t] = s; __syncthreads();
    for (int off = 1; off < 1024; off <<= 1) {
        int v = (t >= off) ? ssum[t - off] : 0;
        __syncthreads();
        ssum[t] += v;
        __syncthreads();
    }
    int run = ssum[t] - s;
    if (t == 1023) g_ucnt[0] = ssum[t];
    for (int j = 0; j < 64; j++) {
        int g = base + j;
        int p = g_present[g];
        g_cidx[g] = run;
        if (p) g_ulist[run] = g;
        run += p;
    }
}
__global__ void tokc_k(const int* __restrict__ ids)
{
    int t = blockIdx.x * blockDim.x + threadIdx.x;
    if (t < NTOK) g_tokc[t] = g_cidx[ids[t]];
}

// ---------------------------------------------------------------------------
// BF16 3-product split GEMM (h*h + l*h + h*l), fp32 accumulate.
// Block 128x256, BK=32, 512 threads (16 warps, 4m x 4n, warp tile 32x64).
// 2-stage double buffer (proven); ldmatrix.x4 fragments; pass-major MMA order.
// Per-element accumulation order (hh, lh, hl per k16, k ascending) is fixed
// => deterministic per gathered row => duplicate-id ties bitwise exact.
// fuse_ln: LayerNorm over the full 256-wide row in the epilogue (per-row
// mean/var via padded smem reduction, fixed order), emit bf16 hi/lo planes.
// ---------------------------------------------------------------------------
#define A_STRB 40
#define A_PL   (128*A_STRB)                 // 5120 bf16
#define B_PL   (256*A_STRB)                 // 10240 bf16
#define BUF_E  (2*A_PL + 2*B_PL)            // 30720 bf16
#define BUF_B  (BUF_E*2)                    // 61440 bytes
#define GEMM_SMEM (2*BUF_B)                 // 122880 bytes

__global__ void __launch_bounds__(512, 1) gemm_bf(
    const float* __restrict__ Araw,                    // non-null -> gathered fp32 A
    const bf16* __restrict__ AhG, const bf16* __restrict__ AlG,
    const bf16* __restrict__ Bh0, const bf16* __restrict__ Bl0,
    float* __restrict__ C0, const float* __restrict__ bias0,
    const bf16* __restrict__ Bh1, const bf16* __restrict__ Bl1,
    float* __restrict__ C1, const float* __restrict__ bias1,
    int Kdim, int Ndim,
    const int* __restrict__ gather,
    int act,                                           // 0=none 1=relu
    const int* __restrict__ ucntp,
    int dual,
    bf16* __restrict__ Ch, bf16* __restrict__ Cl,      // optional split out
    const float* __restrict__ lng, const float* __restrict__ lnb,
    int fuse_ln)
{
    extern __shared__ bf16 smbf[];
    const int bm = blockIdx.x * 128;
    if (bm >= ucntp[0]) return;

    const bf16 *BhG, *BlG;
    const float* bias_;
    float* Cp;
    int bn;
    if (dual && blockIdx.y) { BhG = Bh1; BlG = Bl1; Cp = C1; bias_ = bias1; bn = 0; }
    else { BhG = Bh0; BlG = Bl0; Cp = C0; bias_ = bias0; bn = dual ? 0 : blockIdx.y * 256; }

    const int tid = threadIdx.x;
    const int wid = tid >> 5, lane = tid & 31;
    const int wm = (wid >> 2) * 32, wn = (wid & 3) * 64;
    const int grp = lane >> 2, qd = lane & 3;

    // fill mapping
    const int fa_row = tid >> 2, fa_q = tid & 3;       // A: 128 rows x 4 chunks
    const int fb_row = tid >> 1, fb_h = tid & 1;       // B: 256 rows x 2 chunk-pairs

    int ar = bm + fa_row;
    if (gather) ar = gather[ar];
    const bool gatherA = (Araw != nullptr);
    const float* ApR = gatherA ? (Araw + (size_t)ar * Kdim + fa_q * 8) : nullptr;
    const bf16* AhR = gatherA ? nullptr : (AhG + (size_t)(bm + fa_row) * Kdim + fa_q * 8);
    const bf16* AlR = gatherA ? nullptr : (AlG + (size_t)(bm + fa_row) * Kdim + fa_q * 8);
    const bf16* BhR = BhG + (size_t)(bn + fb_row) * Kdim;
    const bf16* BlR = BlG + (size_t)(bn + fb_row) * Kdim;

    float acc[2][8][4];
#pragma unroll
    for (int mi = 0; mi < 2; mi++)
#pragma unroll
        for (int ni = 0; ni < 8; ni++)
#pragma unroll
            for (int j = 0; j < 4; j++) acc[mi][ni][j] = 0.f;

    const int ktiles = Kdim >> 5;

    const uint32_t smBase = s2u(smbf);
    const uint32_t aFrag = (uint32_t)((wm + (lane & 15)) * (A_STRB*2)) + ((lane >> 4) * 16);
    const uint32_t bFrag = (uint32_t)(2*A_PL*2) +
        (uint32_t)((wn + (lane & 7) + ((lane >> 4) & 1) * 8) * (A_STRB*2)) +
        (((lane >> 3) & 1) * 16);

    auto issueB = [&](int bufo, int kt) {
        uint32_t dh = smBase + bufo + 2*A_PL*2 + (fb_row*A_STRB + fb_h*16) * 2;
        uint32_t dl = dh + B_PL*2;
        const bf16* sh = BhR + kt*32 + fb_h*16;
        const bf16* sl = BlR + kt*32 + fb_h*16;
        cpasync16(dh,      sh);
        cpasync16(dh + 16, sh + 8);
        cpasync16(dl,      sl);
        cpasync16(dl + 16, sl + 8);
    };
    auto issueA = [&](int bufo, int kt) {
        uint32_t dh = smBase + bufo + (fa_row*A_STRB + fa_q*8) * 2;
        cpasync16(dh,            AhR + kt*32);
        cpasync16(dh + A_PL*2,   AlR + kt*32);
    };
    auto stageAgather = [&](int bufo, int kt) {
        float4 v0 = *(const float4*)(ApR + kt*32);
        float4 v1 = *(const float4*)(ApR + kt*32 + 4);
        bf16 h[8], l[8];
        split_bf(v0.x, h[0], l[0]); split_bf(v0.y, h[1], l[1]);
        split_bf(v0.z, h[2], l[2]); split_bf(v0.w, h[3], l[3]);
        split_bf(v1.x, h[4], l[4]); split_bf(v1.y, h[5], l[5]);
        split_bf(v1.z, h[6], l[6]); split_bf(v1.w, h[7], l[7]);
        uint32_t off = bufo + (fa_row*A_STRB + fa_q*8) * 2;
        uint4 ph = make_uint4(pack2(h[0],h[1]), pack2(h[2],h[3]),
                              pack2(h[4],h[5]), pack2(h[6],h[7]));
        uint4 pl = make_uint4(pack2(l[0],l[1]), pack2(l[2],l[3]),
                              pack2(l[4],l[5]), pack2(l[6],l[7]));
        *(uint4*)((char*)smbf + off)           = ph;
        *(uint4*)((char*)smbf + off + A_PL*2)  = pl;
    };

    // prologue: stage 0 -> buffer 0
    issueB(0, 0);
    if (gatherA) stageAgather(0, 0); else issueA(0, 0);
    CP_COMMIT(); CP_WAIT0();
    __syncthreads();

    for (int kt = 0; kt < ktiles; kt++) {
        const int curo = (kt & 1) * BUF_B;
        const int nxto = curo ^ BUF_B;
        const bool more = (kt + 1 < ktiles);
        if (more) {
            issueB(nxto, kt + 1);
            if (gatherA) stageAgather(nxto, kt + 1); else issueA(nxto, kt + 1);
            CP_COMMIT();
        }

#pragma unroll
        for (int k16 = 0; k16 < 2; k16++) {
            uint32_t aH[2][4], aL[2][4];
#pragma unroll
            for (int mi = 0; mi < 2; mi++) {
                uint32_t addr = smBase + curo + aFrag + mi*16*(A_STRB*2) + k16*32;
                ldsm_x4(aH[mi], addr);
                ldsm_x4(aL[mi], addr + A_PL*2);
            }
#pragma unroll
            for (int nig = 0; nig < 4; nig++) {
                uint32_t bH[4], bL[4];
                uint32_t addr = smBase + curo + bFrag + nig*16*(A_STRB*2) + k16*32;
                ldsm_x4(bH, addr);
                ldsm_x4(bL, addr + B_PL*2);
#pragma unroll
                for (int s = 0; s < 2; s++)
#pragma unroll
                    for (int mi = 0; mi < 2; mi++)
                        mma_bf16(acc[mi][nig*2+s], aH[mi], bH[2*s], bH[2*s+1]);
#pragma unroll
                for (int s = 0; s < 2; s++)
#pragma unroll
                    for (int mi = 0; mi < 2; mi++)
                        mma_bf16(acc[mi][nig*2+s], aL[mi], bH[2*s], bH[2*s+1]);
#pragma unroll
                for (int s = 0; s < 2; s++)
#pragma unroll
                    for (int mi = 0; mi < 2; mi++)
                        mma_bf16(acc[mi][nig*2+s], aH[mi], bL[2*s], bL[2*s+1]);
            }
        }

        if (more) CP_WAIT0();
        __syncthreads();
    }

    if (!fuse_ln) {
        // plain epilogue
#pragma unroll
        for (int mi = 0; mi < 2; mi++) {
            const int r0 = bm + wm + mi*16 + grp;
#pragma unroll
            for (int ni = 0; ni < 8; ni++) {
                const int n = bn + wn + ni*8 + qd*2;
                float b0 = bias_ ? bias_[n]   : 0.f;
                float b1 = bias_ ? bias_[n+1] : 0.f;
                float v0 = acc[mi][ni][0] + b0, v1 = acc[mi][ni][1] + b1;
                float v2 = acc[mi][ni][2] + b0, v3 = acc[mi][ni][3] + b1;
                if (act == 1) {
                    v0 = fmaxf(v0, 0.f); v1 = fmaxf(v1, 0.f);
                    v2 = fmaxf(v2, 0.f); v3 = fmaxf(v3, 0.f);
                }
                if (Cp) {
                    *(float2*)&Cp[(size_t)r0 * Ndim + n]     = make_float2(v0, v1);
                    *(float2*)&Cp[(size_t)(r0+8) * Ndim + n] = make_float2(v2, v3);
                }
                if (Ch) {
                    bf16 h0,l0,h1,l1,h2,l2,h3,l3;
                    split_bf(v0,h0,l0); split_bf(v1,h1,l1);
                    split_bf(v2,h2,l2); split_bf(v3,h3,l3);
                    *(uint32_t*)&Ch[(size_t)r0 * Ndim + n]     = pack2(h0, h1);
                    *(uint32_t*)&Ch[(size_t)(r0+8) * Ndim + n] = pack2(h2, h3);
                    *(uint32_t*)&Cl[(size_t)r0 * Ndim + n]     = pack2(l0, l1);
                    *(uint32_t*)&Cl[(size_t)(r0+8) * Ndim + n] = pack2(l2, l3);
                }
            }
        }
    } else {
        // fused LayerNorm epilogue (Ndim == 256, bn == 0; rows fully in-CTA)
        float* red = (float*)smbf;          // [128][17] padded
        float* mus = red + 128*17;
        float* sis = mus + 128;
        const int slot = (wid & 3)*4 + qd;

        // bias add + per-thread row partial sums (fixed ni-ascending order)
#pragma unroll
        for (int mi = 0; mi < 2; mi++) {
            const int lr = wm + mi*16 + grp;
            float s0 = 0.f, s1 = 0.f;
#pragma unroll
            for (int ni = 0; ni < 8; ni++) {
                const int n = wn + ni*8 + qd*2;
                float b0 = bias_[n], b1 = bias_[n+1];
                acc[mi][ni][0] += b0; acc[mi][ni][1] += b1;
                acc[mi][ni][2] += b0; acc[mi][ni][3] += b1;
                s0 += acc[mi][ni][0] + acc[mi][ni][1];
                s1 += acc[mi][ni][2] + acc[mi][ni][3];
            }
            red[lr*17 + slot]     = s0;
            red[(lr+8)*17 + slot] = s1;
        }
        __syncthreads();
        if (tid < 128) {
            float m = 0.f;
#pragma unroll
            for (int s = 0; s < 16; s++) m += red[tid*17 + s];
            mus[tid] = m * (1.f/DM);
        }
        __syncthreads();
#pragma unroll
        for (int mi = 0; mi < 2; mi++) {
            const int lr = wm + mi*16 + grp;
            float mu0 = mus[lr], mu1 = mus[lr+8];
            float s0 = 0.f, s1 = 0.f;
#pragma unroll
            for (int ni = 0; ni < 8; ni++) {
                float c0 = acc[mi][ni][0]-mu0, c1 = acc[mi][ni][1]-mu0;
                float c2 = acc[mi][ni][2]-mu1, c3 = acc[mi][ni][3]-mu1;
                s0 += c0*c0 + c1*c1;
                s1 += c2*c2 + c3*c3;
            }
            red[lr*17 + slot]     = s0;
            red[(lr+8)*17 + slot] = s1;
        }
        __syncthreads();
        if (tid < 128) {
            float v = 0.f;
#pragma unroll
            for (int s = 0; s < 16; s++) v += red[tid*17 + s];
            sis[tid] = rsqrtf(v * (1.f/DM) + 1e-5f);
        }
        __syncthreads();
#pragma unroll
        for (int mi = 0; mi < 2; mi++) {
            const int lr = wm + mi*16 + grp;
            const int r0 = bm + lr;
            float mu0 = mus[lr], is0 = sis[lr];
            float mu1 = mus[lr+8], is1 = sis[lr+8];
#pragma unroll
            for (int ni = 0; ni < 8; ni++) {
                const int n = wn + ni*8 + qd*2;
                float g0 = lng[n], g1 = lng[n+1], e0 = lnb[n], e1 = lnb[n+1];
                float v0 = g0*(acc[mi][ni][0]-mu0)*is0 + e0;
                float v1 = g1*(acc[mi][ni][1]-mu0)*is0 + e1;
                float v2 = g0*(acc[mi][ni][2]-mu1)*is1 + e0;
                float v3 = g1*(acc[mi][ni][3]-mu1)*is1 + e1;
                bf16 h0,l0,h1,l1,h2,l2,h3,l3;
                split_bf(v0,h0,l0); split_bf(v1,h1,l1);
                split_bf(v2,h2,l2); split_bf(v3,h3,l3);
                *(uint32_t*)&Ch[(size_t)r0 * Ndim + n]     = pack2(h0, h1);
                *(uint32_t*)&Ch[(size_t)(r0+8) * Ndim + n] = pack2(h2, h3);
                *(uint32_t*)&Cl[(size_t)r0 * Ndim + n]     = pack2(l0, l1);
                *(uint32_t*)&Cl[(size_t)(r0+8) * Ndim + n] = pack2(l2, l3);
            }
        }
    }
}

// ---------------------------------------------------------------------------
// Per-(b,l) precompute
// ---------------------------------------------------------------------------
__global__ void prep_k(const float* __restrict__ v, const float* __restrict__ tv,
                       const float* __restrict__ am_w1, const float* __restrict__ am_b1,
                       const float* __restrict__ wq)
{
    __shared__ float tvs[DM];
    __shared__ float qs[DM];
    int bl = blockIdx.x, d = threadIdx.x;
    float t0 = tv[(size_t)bl*DM + d];
    tvs[d] = t0;
    qs[d]  = t0 + v[(size_t)bl*DM + d];
    __syncthreads();
    float t = am_b1[d], q = 0.f;
    for (int k = 0; k < DM; k++) {
        t = fmaf(tvs[k], am_w1[k*DM + d], t);
        q = fmaf(qs[k],  wq  [k*DM + d], q);
    }
    g_T [(size_t)bl*DM + d] = t;
    g_QW[(size_t)bl*DM + d] = q;
}

// ---------------------------------------------------------------------------
// Per-token score
// ---------------------------------------------------------------------------
__global__ void score2_k(const float* __restrict__ am_w2)
{
    int tok  = blockIdx.x * 8 + (threadIdx.x >> 5);
    int lane = threadIdx.x & 31;
    int c  = g_tokc[tok];
    int bl = tok >> 6;
    const float* s2 = g_S2 + (size_t)c * DM;
    const float* tt = g_T  + (size_t)bl * DM;
    float s = 0.f;
#pragma unroll
    for (int d = lane; d < DM; d += 32)
        s = fmaf(tanhf(s2[d] + tt[d]), am_w2[d], s);
    for (int o = 16; o > 0; o >>= 1) s += __shfl_down_sync(0xffffffffu, s, o);
    if (lane == 0) g_S[tok] = s;
}

// ---------------------------------------------------------------------------
// Per-visit stable sort (softmax->mask->top_k(64 of 64) equivalent)
// ---------------------------------------------------------------------------
__global__ void select_k(const int* __restrict__ masks)
{
    int bl = blockIdx.x, j = threadIdx.x;
    __shared__ float key[64];
    int tok = bl*64 + j;
    float k_ = masks[tok] ? g_S[tok] : neg_inf();
    key[j] = k_; __syncthreads();
    int rank = 0;
    for (int m = 0; m < 64; m++) {
        float o = key[m];
        rank += (o > k_) || (o == k_ && m < j);
    }
    g_selslot[bl*64 + rank] = (bl % LSEQ) * NBLK + j;
}

// ---------------------------------------------------------------------------
// Sequential memory recurrence (with guarded kvec prefetch: next candidate's
// loads are issued before the current shuffle-reduce chain).
// ---------------------------------------------------------------------------
__global__ void recur_k(const int* __restrict__ ids, const int* __restrict__ masks,
                        const int* __restrict__ lens)
{
    int b = blockIdx.x, tid = threadIdx.x;
    __shared__ __align__(16) float qw[DM];
    __shared__ int cslot[64], cmask[64];
    __shared__ int nslot[64], nmask[64];
    __shared__ int dslot[128], dmask[128], dcid[128];
    __shared__ float ev[128];

    if (tid < 64) {
        int slot = g_selslot[(b*LSEQ + 0)*64 + tid];
        cslot[tid] = slot;
        cmask[tid] = masks[b*SLOTS + slot];
    }
    int lb = lens[b];
    __syncthreads();

    int w = tid >> 5, lane = tid & 31;

    for (int t = 1; t < LSEQ; t++) {
        qw[tid] = g_QW[(size_t)(b*LSEQ + t)*DM + tid];
        if (tid < 128) {
            int slot = (tid < 64) ? cslot[tid] : g_selslot[(b*LSEQ + t)*64 + (tid - 64)];
            dslot[tid] = slot;
            dmask[tid] = (tid < 64) ? cmask[tid] : masks[b*SLOTS + slot];
            dcid [tid] = g_tokc[b*SLOTS + slot];
        }
        __syncthreads();

        const float4* q4 = (const float4*)qw;
        float4 q0 = q4[lane*2], q1 = q4[lane*2 + 1];
        const float4* kv0 = (const float4*)(g_KV + (size_t)dcid[w] * DM);
        float4 k0 = kv0[lane*2], k1 = kv0[lane*2 + 1];
        for (int c = w; c < 128; c += 8) {
            const bool hasnext = (c + 8 < 128);
            float4 n0, n1;
            if (hasnext) {
                const float4* kvn = (const float4*)(g_KV + (size_t)dcid[c + 8] * DM);
                n0 = kvn[lane*2]; n1 = kvn[lane*2 + 1];
            }
            float s = k0.x*q0.x + k0.y*q0.y + k0.z*q0.z + k0.w*q0.w
                    + k1.x*q1.x + k1.y*q1.y + k1.z*q1.z + k1.w*q1.w;
            for (int o = 16; o > 0; o >>= 1) s += __shfl_down_sync(0xffffffffu, s, o);
            if (lane == 0) ev[c] = s;
            if (hasnext) { k0 = n0; k1 = n1; }
        }
        __syncthreads();

        if (tid < 128) {
            float k_ = dmask[tid] ? ev[tid] : neg_inf();
            int rank = 0;
            for (int m = 0; m < 128; m++) {
                float o = dmask[m] ? ev[m] : neg_inf();
                rank += (o > k_) || (o == k_ && m < tid);
            }
            if (rank < 64) { nslot[rank] = dslot[tid]; nmask[rank] = dmask[tid]; }
        }
        __syncthreads();
        if (tid < 64) {
            cslot[tid] = nslot[tid];
            cmask[tid] = nmask[tid];
            if (t == lb - 1) g_fslot[b*64 + tid] = nslot[tid];
        }
        __syncthreads();
    }
}

// ---------------------------------------------------------------------------
// Pools (VT reconstructed as hi+lo; max-pool path, 1e-3 tolerance)
// ---------------------------------------------------------------------------
__global__ void final_k(const float* __restrict__ tv, const int* __restrict__ ids,
                        const int* __restrict__ lens)
{
    int b = blockIdx.x, d = threadIdx.x;
    int lb = lens[b];
    float mx = neg_inf();
    for (int l = 0; l < lb; l++) mx = fmaxf(mx, tv[((size_t)b*LSEQ + l)*DM + d]);
    g_vfin[b*DM + d] = mx;
    float mv = neg_inf();
    for (int m = 0; m < 64; m++) {
        int c = g_tokc[b*SLOTS + g_fslot[b*64 + m]];
        float vt = __bfloat162float(g_VTh[(size_t)c*DM + d])
                 + __bfloat162float(g_VTl[(size_t)c*DM + d]);
        mv = fmaxf(mv, vt);
    }
    g_mfin[b*DM + d] = mv;
    if (d < 64) g_fid[b*64 + d] = ids[b*SLOTS + g_fslot[b*64 + d]];
}

// ---------------------------------------------------------------------------
// Output head + flatten
// ---------------------------------------------------------------------------
__global__ void out_k(const float* __restrict__ ow, const float* __restrict__ ob,
                      float* __restrict__ out, int out_size)
{
    int tid = threadIdx.x;
    if (tid < 32) {
        int b = tid >> 1, o = tid & 1;
        float v = ob[o];
        for (int d = 0; d < DM; d++) v = fmaf(g_vfin[b*DM + d], ow[d*2 + o], v);
        for (int d = 0; d < DM; d++) v = fmaf(g_mfin[b*DM + d], ow[(DM + d)*2 + o], v);
        if (tid < out_size) out[tid] = v;
    }
    for (int i = tid; i < BSZ*64; i += blockDim.x)
        if (32 + i < out_size) out[32 + i] = (float)g_fid[i];
    for (int i = 32 + BSZ*64 + tid; i < out_size; i += blockDim.x)
        out[i] = 0.f;
}

// ---------------------------------------------------------------------------
// Launch
// ---------------------------------------------------------------------------
extern "C" void kernel_launch(void* const* d_in, const int* in_sizes, int n_in,
                              void* d_out, int out_size)
{
    const float* v_all  = (const float*)d_in[0];
    const float* tv_all = (const float*)d_in[1];
    const float* emb    = (const float*)d_in[2];
    const float* w1     = (const float*)d_in[3];
    const float* b1     = (const float*)d_in[4];
    const float* w2     = (const float*)d_in[5];
    const float* b2     = (const float*)d_in[6];
    const float* gam    = (const float*)d_in[7];
    const float* bet    = (const float*)d_in[8];
    const float* wq     = (const float*)d_in[9];
    const float* wk     = (const float*)d_in[10];
    const float* amw1   = (const float*)d_in[11];
    const float* amb1   = (const float*)d_in[12];
    const float* amw2   = (const float*)d_in[13];
    const float* ow     = (const float*)d_in[14];
    const float* ob     = (const float*)d_in[15];
    const int*   itxt   = (const int*)d_in[16];
    const int*   mtxt   = (const int*)d_in[17];
    const int*   lens   = (const int*)d_in[18];
    float* out = (float*)d_out;

    bf16 *pHh, *pHl, *pVTh, *pVTl, *pBh, *pBl;
    float *pKV, *pS2;
    int *pU, *pUL;
    cudaGetSymbolAddress((void**)&pHh,  g_Hh);
    cudaGetSymbolAddress((void**)&pHl,  g_Hl);
    cudaGetSymbolAddress((void**)&pVTh, g_VTh);
    cudaGetSymbolAddress((void**)&pVTl, g_VTl);
    cudaGetSymbolAddress((void**)&pKV,  g_KV);
    cudaGetSymbolAddress((void**)&pS2,  g_S2);
    cudaGetSymbolAddress((void**)&pBh,  g_Bh);
    cudaGetSymbolAddress((void**)&pBl,  g_Bl);
    cudaGetSymbolAddress((void**)&pU,   g_ucnt);
    cudaGetSymbolAddress((void**)&pUL,  g_ulist);

    cudaFuncSetAttribute(gemm_bf, cudaFuncAttributeMaxDynamicSharedMemorySize, GEMM_SMEM);

    // 0..2: weight transpose+split + dedup (gemm1 at profiled launch index 3)
    prep0_k<<<640, 256>>>(w1, w2, wk, amw1 + DM*DM);
    mark_k<<<NTOK/256, 256>>>(itxt);
    scanall_k<<<1, 1024>>>();

    // 3: GEMM1: relu(emb[gather] @ w1 + b1) -> bf16 planes g_Hh/g_Hl
    gemm_bf<<<dim3(NVOC/128, 2), 512, GEMM_SMEM>>>(
        emb, nullptr, nullptr,
        pBh + OFF_W1, pBl + OFF_W1, nullptr, b1,
        nullptr, nullptr, nullptr, nullptr,
        KD, DH, pUL, 1, pU, 0, pHh, pHl, nullptr, nullptr, 0);

    tokc_k<<<NTOK/256, 256>>>(itxt);
    prep_k<<<NBL, DM>>>(v_all, tv_all, amw1, amb1, wq);

    // GEMM2 + fused LayerNorm: VT = LN(Hplanes @ w2 + b2) -> g_VTh/g_VTl
    gemm_bf<<<dim3(NVOC/128, 1), 512, GEMM_SMEM>>>(
        nullptr, pHh, pHl,
        pBh + OFF_W2, pBl + OFF_W2, nullptr, b2,
        nullptr, nullptr, nullptr, nullptr,
        DH, DM, nullptr, 0, pU, 0, pVTh, pVTl, gam, bet, 1);

    // GEMM3+4 fused: KV = VT @ wk ; S2 = VT @ am_w1[D:]
    gemm_bf<<<dim3(NVOC/128, 2), 512, GEMM_SMEM>>>(
        nullptr, pVTh, pVTl,
        pBh + OFF_WK, pBl + OFF_WK, pKV, nullptr,
        pBh + OFF_AM, pBl + OFF_AM, pS2, nullptr,
        DM, DM, nullptr, 0, pU, 1, nullptr, nullptr, nullptr, nullptr, 0);

    // score + selection + recurrence + pooling + head
    score2_k<<<NTOK/8, 256>>>(amw2);
    select_k<<<NBL, 64>>>(mtxt);
    recur_k<<<BSZ, 256>>>(itxt, mtxt, lens);
    final_k<<<BSZ, DM>>>(tv_all, itxt, lens);
    out_k<<<1, 256>>>(ow, ob, out, out_size);
}

// round 13
// speedup vs baseline: 1.8247x; 1.2366x over previous
#include <cuda_runtime.h>
#include <cuda_bf16.h>
#include <math.h>
#include <stdint.h>

// ---------------------------------------------------------------------------
// Problem constants
// ---------------------------------------------------------------------------
#define BSZ   16
#define LSEQ  50
#define NBLK  64
#define DM    256
#define DH    512
#define KD    768
#define NVOC  65536
#define NTOK  (BSZ*LSEQ*NBLK)   // 51200
#define NBL   (BSZ*LSEQ)        // 800
#define SLOTS (LSEQ*NBLK)       // 3200 per batch

typedef __nv_bfloat16 bf16;

__device__ __forceinline__ float neg_inf() { return __int_as_float(0xff800000); }

// ---------------------------------------------------------------------------
// Scratch (static device globals; no allocation)
// ---------------------------------------------------------------------------
__device__ __align__(128) bf16  g_Hh[(size_t)NVOC*DH];  // relu hidden, bf16-hi
__device__ __align__(128) bf16  g_Hl[(size_t)NVOC*DH];  // relu hidden, bf16-lo
__device__ __align__(128) bf16  g_VTh[(size_t)NVOC*DM]; // v_text hi (post-LN)
__device__ __align__(128) bf16  g_VTl[(size_t)NVOC*DM]; // v_text lo (post-LN)
__device__ __align__(128) float g_KV[(size_t)NVOC*DM];  // v_text @ wk
__device__ __align__(128) float g_S2[(size_t)NVOC*DM];  // v_text @ am_w1[D:]
__device__ __align__(128) float g_S [NTOK];
__device__ __align__(128) float g_T [NBL*DM];
__device__ __align__(128) float g_QW[NBL*DM];

// pre-split TRANSPOSED weight planes ([N][K], k-contiguous): w1 | w2 | wk | am
#define OFF_W1 0
#define OFF_W2 393216
#define OFF_WK 524288
#define OFF_AM 589824
#define TOTW   655360
__device__ __align__(128) bf16 g_Bh[TOTW];
__device__ __align__(128) bf16 g_Bl[TOTW];

__device__ int   g_present[NVOC];
__device__ int   g_cidx[NVOC];
__device__ int   g_ulist[NVOC];
__device__ int   g_bsum[64];
__device__ int   g_boff[64];
__device__ int   g_ucnt[1];
__device__ int   g_tokc[NTOK];
__device__ int   g_selslot[NTOK];
__device__ int   g_fslot[BSZ*64];
__device__ int   g_fid  [BSZ*64];
__device__ __align__(128) float g_vfin[BSZ*DM];
__device__ __align__(128) float g_mfin[BSZ*DM];

// ---------------------------------------------------------------------------
// helpers
// ---------------------------------------------------------------------------
__device__ __forceinline__ void split_bf(float x, bf16& h, bf16& l)
{
    h = __float2bfloat16_rn(x);
    l = __float2bfloat16_rn(x - __bfloat162float(h));
}
__device__ __forceinline__ uint32_t pack2(bf16 a, bf16 b)
{
    return (uint32_t)__bfloat16_as_ushort(a) | ((uint32_t)__bfloat16_as_ushort(b) << 16);
}
__device__ __forceinline__ void mma_bf16(float c[4], const uint32_t a[4],
                                         uint32_t b0, uint32_t b1)
{
    asm volatile(
        "mma.sync.aligned.m16n8k16.row.col.f32.bf16.bf16.f32 "
        "{%0,%1,%2,%3}, {%4,%5,%6,%7}, {%8,%9}, {%0,%1,%2,%3};"
        : "+f"(c[0]), "+f"(c[1]), "+f"(c[2]), "+f"(c[3])
        : "r"(a[0]), "r"(a[1]), "r"(a[2]), "r"(a[3]), "r"(b0), "r"(b1));
}
__device__ __forceinline__ void ldsm_x4(uint32_t r[4], uint32_t saddr)
{
    asm volatile("ldmatrix.sync.aligned.m8n8.x4.shared.b16 {%0,%1,%2,%3}, [%4];"
        : "=r"(r[0]), "=r"(r[1]), "=r"(r[2]), "=r"(r[3]) : "r"(saddr));
}
__device__ __forceinline__ uint32_t s2u(const void* p)
{
    return (uint32_t)__cvta_generic_to_shared(p);
}
__device__ __forceinline__ void cpasync16(uint32_t dst, const void* src)
{
    asm volatile("cp.async.ca.shared.global [%0], [%1], 16;" :: "r"(dst), "l"(src));
}
#define CP_COMMIT() asm volatile("cp.async.commit_group;")
#define CP_WAIT0()  asm volatile("cp.async.wait_group 0;")

// ---------------------------------------------------------------------------
// Launch 0: zero present/ulist + tiled transpose-split of all weights
// ---------------------------------------------------------------------------
__global__ void prep0_k(const float* __restrict__ w1, const float* __restrict__ w2,
                        const float* __restrict__ wk, const float* __restrict__ am1)
{
    int bid = blockIdx.x, tid = threadIdx.x;
    if (bid < 256) g_present[bid*256 + tid] = 0;
    else if (bid < 512) g_ulist[(bid-256)*256 + tid] = 0;

    const float* W; bf16 *oh, *ol; int K, N, kt, nt;
    int id = bid;
    if (id < 384)      { W = w1;  oh = g_Bh+OFF_W1; ol = g_Bl+OFF_W1; K = KD; N = DH; kt = id % 24; nt = id / 24; }
    else if (id < 512) { id -= 384; W = w2;  oh = g_Bh+OFF_W2; ol = g_Bl+OFF_W2; K = DH; N = DM; kt = id % 16; nt = id / 16; }
    else if (id < 576) { id -= 512; W = wk;  oh = g_Bh+OFF_WK; ol = g_Bl+OFF_WK; K = DM; N = DM; kt = id % 8;  nt = id / 8; }
    else               { id -= 576; W = am1; oh = g_Bh+OFF_AM; ol = g_Bl+OFF_AM; K = DM; N = DM; kt = id % 8;  nt = id / 8; }

    __shared__ float t[32][33];
    int tx = tid & 31, ty = tid >> 5;
#pragma unroll
    for (int i = 0; i < 4; i++) {
        int k = kt*32 + ty + i*8, n = nt*32 + tx;
        t[ty + i*8][tx] = W[(size_t)k*N + n];
    }
    __syncthreads();
#pragma unroll
    for (int i = 0; i < 4; i++) {
        int n = nt*32 + ty + i*8, k = kt*32 + tx;
        split_bf(t[tx][ty + i*8], oh[(size_t)n*K + k], ol[(size_t)n*K + k]);
    }
}
__global__ void mark_k(const int* __restrict__ ids)
{
    int t = blockIdx.x * blockDim.x + threadIdx.x;
    if (t < NTOK) g_present[ids[t]] = 1;
}
// parallel scan: 64 blocks x 1024 local scan -> tiny offset pass -> compact
__global__ void scan1_k()
{
    __shared__ int s[1024];
    int t = threadIdx.x, g = blockIdx.x * 1024 + t;
    int p = g_present[g];
    s[t] = p; __syncthreads();
    for (int off = 1; off < 1024; off <<= 1) {
        int v = (t >= off) ? s[t - off] : 0;
        __syncthreads();
        s[t] += v;
        __syncthreads();
    }
    g_cidx[g] = s[t] - p;
    if (t == 1023) g_bsum[blockIdx.x] = s[t];
}
__global__ void scan2_k()
{
    if (threadIdx.x == 0) {
        int run = 0;
        for (int i = 0; i < 64; i++) { g_boff[i] = run; run += g_bsum[i]; }
        g_ucnt[0] = run;
    }
}
__global__ void scan3_k()
{
    int t = threadIdx.x, g = blockIdx.x * 1024 + t;
    int c = g_cidx[g] + g_boff[blockIdx.x];
    g_cidx[g] = c;
    if (g_present[g]) g_ulist[c] = g;
}
__global__ void tokc_k(const int* __restrict__ ids)
{
    int t = blockIdx.x * blockDim.x + threadIdx.x;
    if (t < NTOK) g_tokc[t] = g_cidx[ids[t]];
}

// ---------------------------------------------------------------------------
// BF16 3-product split GEMM (h*h + l*h + h*l), fp32 accumulate.
// Block 128x256, BK=32, 512 threads (16 warps, 4m x 4n, warp tile 32x64).
// 2-stage double buffer; ldmatrix.x4 fragments; pass-major MMA order.
// fuse_ln: full-row LayerNorm epilogue, emit bf16 hi/lo planes.
// ---------------------------------------------------------------------------
#define A_STRB 40
#define A_PL   (128*A_STRB)                 // 5120 bf16
#define B_PL   (256*A_STRB)                 // 10240 bf16
#define BUF_E  (2*A_PL + 2*B_PL)            // 30720 bf16
#define BUF_B  (BUF_E*2)                    // 61440 bytes
#define GEMM_SMEM (2*BUF_B)                 // 122880 bytes

__global__ void __launch_bounds__(512, 1) gemm_bf(
    const float* __restrict__ Araw,
    const bf16* __restrict__ AhG, const bf16* __restrict__ AlG,
    const bf16* __restrict__ Bh0, const bf16* __restrict__ Bl0,
    float* __restrict__ C0, const float* __restrict__ bias0,
    const bf16* __restrict__ Bh1, const bf16* __restrict__ Bl1,
    float* __restrict__ C1, const float* __restrict__ bias1,
    int Kdim, int Ndim,
    const int* __restrict__ gather,
    int act,
    const int* __restrict__ ucntp,
    int dual,
    bf16* __restrict__ Ch, bf16* __restrict__ Cl,
    const float* __restrict__ lng, const float* __restrict__ lnb,
    int fuse_ln)
{
    extern __shared__ bf16 smbf[];
    const int bm = blockIdx.x * 128;
    if (bm >= ucntp[0]) return;

    const bf16 *BhG, *BlG;
    const float* bias_;
    float* Cp;
    int bn;
    if (dual && blockIdx.y) { BhG = Bh1; BlG = Bl1; Cp = C1; bias_ = bias1; bn = 0; }
    else { BhG = Bh0; BlG = Bl0; Cp = C0; bias_ = bias0; bn = dual ? 0 : blockIdx.y * 256; }

    const int tid = threadIdx.x;
    const int wid = tid >> 5, lane = tid & 31;
    const int wm = (wid >> 2) * 32, wn = (wid & 3) * 64;
    const int grp = lane >> 2, qd = lane & 3;

    const int fa_row = tid >> 2, fa_q = tid & 3;
    const int fb_row = tid >> 1, fb_h = tid & 1;

    int ar = bm + fa_row;
    if (gather) ar = gather[ar];
    const bool gatherA = (Araw != nullptr);
    const float* ApR = gatherA ? (Araw + (size_t)ar * Kdim + fa_q * 8) : nullptr;
    const bf16* AhR = gatherA ? nullptr : (AhG + (size_t)(bm + fa_row) * Kdim + fa_q * 8);
    const bf16* AlR = gatherA ? nullptr : (AlG + (size_t)(bm + fa_row) * Kdim + fa_q * 8);
    const bf16* BhR = BhG + (size_t)(bn + fb_row) * Kdim;
    const bf16* BlR = BlG + (size_t)(bn + fb_row) * Kdim;

    float acc[2][8][4];
#pragma unroll
    for (int mi = 0; mi < 2; mi++)
#pragma unroll
        for (int ni = 0; ni < 8; ni++)
#pragma unroll
            for (int j = 0; j < 4; j++) acc[mi][ni][j] = 0.f;

    const int ktiles = Kdim >> 5;

    const uint32_t smBase = s2u(smbf);
    const uint32_t aFrag = (uint32_t)((wm + (lane & 15)) * (A_STRB*2)) + ((lane >> 4) * 16);
    const uint32_t bFrag = (uint32_t)(2*A_PL*2) +
        (uint32_t)((wn + (lane & 7) + ((lane >> 4) & 1) * 8) * (A_STRB*2)) +
        (((lane >> 3) & 1) * 16);

    auto issueB = [&](int bufo, int kt) {
        uint32_t dh = smBase + bufo + 2*A_PL*2 + (fb_row*A_STRB + fb_h*16) * 2;
        uint32_t dl = dh + B_PL*2;
        const bf16* sh = BhR + kt*32 + fb_h*16;
        const bf16* sl = BlR + kt*32 + fb_h*16;
        cpasync16(dh,      sh);
        cpasync16(dh + 16, sh + 8);
        cpasync16(dl,      sl);
        cpasync16(dl + 16, sl + 8);
    };
    auto issueA = [&](int bufo, int kt) {
        uint32_t dh = smBase + bufo + (fa_row*A_STRB + fa_q*8) * 2;
        cpasync16(dh,            AhR + kt*32);
        cpasync16(dh + A_PL*2,   AlR + kt*32);
    };
    auto stageAgather = [&](int bufo, int kt) {
        float4 v0 = *(const float4*)(ApR + kt*32);
        float4 v1 = *(const float4*)(ApR + kt*32 + 4);
        bf16 h[8], l[8];
        split_bf(v0.x, h[0], l[0]); split_bf(v0.y, h[1], l[1]);
        split_bf(v0.z, h[2], l[2]); split_bf(v0.w, h[3], l[3]);
        split_bf(v1.x, h[4], l[4]); split_bf(v1.y, h[5], l[5]);
        split_bf(v1.z, h[6], l[6]); split_bf(v1.w, h[7], l[7]);
        uint32_t off = bufo + (fa_row*A_STRB + fa_q*8) * 2;
        uint4 ph = make_uint4(pack2(h[0],h[1]), pack2(h[2],h[3]),
                              pack2(h[4],h[5]), pack2(h[6],h[7]));
        uint4 pl = make_uint4(pack2(l[0],l[1]), pack2(l[2],l[3]),
                              pack2(l[4],l[5]), pack2(l[6],l[7]));
        *(uint4*)((char*)smbf + off)           = ph;
        *(uint4*)((char*)smbf + off + A_PL*2)  = pl;
    };

    issueB(0, 0);
    if (gatherA) stageAgather(0, 0); else issueA(0, 0);
    CP_COMMIT(); CP_WAIT0();
    __syncthreads();

    for (int kt = 0; kt < ktiles; kt++) {
        const int curo = (kt & 1) * BUF_B;
        const int nxto = curo ^ BUF_B;
        const bool more = (kt + 1 < ktiles);
        if (more) {
            issueB(nxto, kt + 1);
            if (gatherA) stageAgather(nxto, kt + 1); else issueA(nxto, kt + 1);
            CP_COMMIT();
        }

#pragma unroll
        for (int k16 = 0; k16 < 2; k16++) {
            uint32_t aH[2][4], aL[2][4];
#pragma unroll
            for (int mi = 0; mi < 2; mi++) {
                uint32_t addr = smBase + curo + aFrag + mi*16*(A_STRB*2) + k16*32;
                ldsm_x4(aH[mi], addr);
                ldsm_x4(aL[mi], addr + A_PL*2);
            }
#pragma unroll
            for (int nig = 0; nig < 4; nig++) {
                uint32_t bH[4], bL[4];
                uint32_t addr = smBase + curo + bFrag + nig*16*(A_STRB*2) + k16*32;
                ldsm_x4(bH, addr);
                ldsm_x4(bL, addr + B_PL*2);
#pragma unroll
                for (int s = 0; s < 2; s++)
#pragma unroll
                    for (int mi = 0; mi < 2; mi++)
                        mma_bf16(acc[mi][nig*2+s], aH[mi], bH[2*s], bH[2*s+1]);
#pragma unroll
                for (int s = 0; s < 2; s++)
#pragma unroll
                    for (int mi = 0; mi < 2; mi++)
                        mma_bf16(acc[mi][nig*2+s], aL[mi], bH[2*s], bH[2*s+1]);
#pragma unroll
                for (int s = 0; s < 2; s++)
#pragma unroll
                    for (int mi = 0; mi < 2; mi++)
                        mma_bf16(acc[mi][nig*2+s], aH[mi], bL[2*s], bL[2*s+1]);
            }
        }

        if (more) CP_WAIT0();
        __syncthreads();
    }

    if (!fuse_ln) {
#pragma unroll
        for (int mi = 0; mi < 2; mi++) {
            const int r0 = bm + wm + mi*16 + grp;
#pragma unroll
            for (int ni = 0; ni < 8; ni++) {
                const int n = bn + wn + ni*8 + qd*2;
                float b0 = bias_ ? bias_[n]   : 0.f;
                float b1 = bias_ ? bias_[n+1] : 0.f;
                float v0 = acc[mi][ni][0] + b0, v1 = acc[mi][ni][1] + b1;
                float v2 = acc[mi][ni][2] + b0, v3 = acc[mi][ni][3] + b1;
                if (act == 1) {
                    v0 = fmaxf(v0, 0.f); v1 = fmaxf(v1, 0.f);
                    v2 = fmaxf(v2, 0.f); v3 = fmaxf(v3, 0.f);
                }
                if (Cp) {
                    *(float2*)&Cp[(size_t)r0 * Ndim + n]     = make_float2(v0, v1);
                    *(float2*)&Cp[(size_t)(r0+8) * Ndim + n] = make_float2(v2, v3);
                }
                if (Ch) {
                    bf16 h0,l0,h1,l1,h2,l2,h3,l3;
                    split_bf(v0,h0,l0); split_bf(v1,h1,l1);
                    split_bf(v2,h2,l2); split_bf(v3,h3,l3);
                    *(uint32_t*)&Ch[(size_t)r0 * Ndim + n]     = pack2(h0, h1);
                    *(uint32_t*)&Ch[(size_t)(r0+8) * Ndim + n] = pack2(h2, h3);
                    *(uint32_t*)&Cl[(size_t)r0 * Ndim + n]     = pack2(l0, l1);
                    *(uint32_t*)&Cl[(size_t)(r0+8) * Ndim + n] = pack2(l2, l3);
                }
            }
        }
    } else {
        float* red = (float*)smbf;          // [128][17] padded
        float* mus = red + 128*17;
        float* sis = mus + 128;
        const int slot = (wid & 3)*4 + qd;

#pragma unroll
        for (int mi = 0; mi < 2; mi++) {
            const int lr = wm + mi*16 + grp;
            float s0 = 0.f, s1 = 0.f;
#pragma unroll
            for (int ni = 0; ni < 8; ni++) {
                const int n = wn + ni*8 + qd*2;
                float b0 = bias_[n], b1 = bias_[n+1];
                acc[mi][ni][0] += b0; acc[mi][ni][1] += b1;
                acc[mi][ni][2] += b0; acc[mi][ni][3] += b1;
                s0 += acc[mi][ni][0] + acc[mi][ni][1];
                s1 += acc[mi][ni][2] + acc[mi][ni][3];
            }
            red[lr*17 + slot]     = s0;
            red[(lr+8)*17 + slot] = s1;
        }
        __syncthreads();
        if (tid < 128) {
            float m = 0.f;
#pragma unroll
            for (int s = 0; s < 16; s++) m += red[tid*17 + s];
            mus[tid] = m * (1.f/DM);
        }
        __syncthreads();
#pragma unroll
        for (int mi = 0; mi < 2; mi++) {
            const int lr = wm + mi*16 + grp;
            float mu0 = mus[lr], mu1 = mus[lr+8];
            float s0 = 0.f, s1 = 0.f;
#pragma unroll
            for (int ni = 0; ni < 8; ni++) {
                float c0 = acc[mi][ni][0]-mu0, c1 = acc[mi][ni][1]-mu0;
                float c2 = acc[mi][ni][2]-mu1, c3 = acc[mi][ni][3]-mu1;
                s0 += c0*c0 + c1*c1;
                s1 += c2*c2 + c3*c3;
            }
            red[lr*17 + slot]     = s0;
            red[(lr+8)*17 + slot] = s1;
        }
        __syncthreads();
        if (tid < 128) {
            float v = 0.f;
#pragma unroll
            for (int s = 0; s < 16; s++) v += red[tid*17 + s];
            sis[tid] = rsqrtf(v * (1.f/DM) + 1e-5f);
        }
        __syncthreads();
#pragma unroll
        for (int mi = 0; mi < 2; mi++) {
            const int lr = wm + mi*16 + grp;
            const int r0 = bm + lr;
            float mu0 = mus[lr], is0 = sis[lr];
            float mu1 = mus[lr+8], is1 = sis[lr+8];
#pragma unroll
            for (int ni = 0; ni < 8; ni++) {
                const int n = wn + ni*8 + qd*2;
                float g0 = lng[n], g1 = lng[n+1], e0 = lnb[n], e1 = lnb[n+1];
                float v0 = g0*(acc[mi][ni][0]-mu0)*is0 + e0;
                float v1 = g1*(acc[mi][ni][1]-mu0)*is0 + e1;
                float v2 = g0*(acc[mi][ni][2]-mu1)*is1 + e0;
                float v3 = g1*(acc[mi][ni][3]-mu1)*is1 + e1;
                bf16 h0,l0,h1,l1,h2,l2,h3,l3;
                split_bf(v0,h0,l0); split_bf(v1,h1,l1);
                split_bf(v2,h2,l2); split_bf(v3,h3,l3);
                *(uint32_t*)&Ch[(size_t)r0 * Ndim + n]     = pack2(h0, h1);
                *(uint32_t*)&Ch[(size_t)(r0+8) * Ndim + n] = pack2(h2, h3);
                *(uint32_t*)&Cl[(size_t)r0 * Ndim + n]     = pack2(l0, l1);
                *(uint32_t*)&Cl[(size_t)(r0+8) * Ndim + n] = pack2(l2, l3);
            }
        }
    }
}

// ---------------------------------------------------------------------------
// Per-(b,l) precompute
// ---------------------------------------------------------------------------
__global__ void prep_k(const float* __restrict__ v, const float* __restrict__ tv,
                       const float* __restrict__ am_w1, const float* __restrict__ am_b1,
                       const float* __restrict__ wq)
{
    __shared__ float tvs[DM];
    __shared__ float qs[DM];
    int bl = blockIdx.x, d = threadIdx.x;
    float t0 = tv[(size_t)bl*DM + d];
    tvs[d] = t0;
    qs[d]  = t0 + v[(size_t)bl*DM + d];
    __syncthreads();
    float t = am_b1[d], q = 0.f;
    for (int k = 0; k < DM; k++) {
        t = fmaf(tvs[k], am_w1[k*DM + d], t);
        q = fmaf(qs[k],  wq  [k*DM + d], q);
    }
    g_T [(size_t)bl*DM + d] = t;
    g_QW[(size_t)bl*DM + d] = q;
}

// ---------------------------------------------------------------------------
// Per-token score (float4 loads; fixed per-(cidx,bl) accumulation order)
// ---------------------------------------------------------------------------
__global__ void score2_k(const float* __restrict__ am_w2)
{
    int tok  = blockIdx.x * 8 + (threadIdx.x >> 5);
    int lane = threadIdx.x & 31;
    int c  = g_tokc[tok];
    int bl = tok >> 6;
    const float4* s24 = (const float4*)(g_S2 + (size_t)c * DM);
    const float4* tt4 = (const float4*)(g_T  + (size_t)bl * DM);
    const float4* w4  = (const float4*)am_w2;
    float4 a0 = s24[lane*2],   a1 = s24[lane*2+1];
    float4 t0 = tt4[lane*2],   t1 = tt4[lane*2+1];
    float4 w0 = w4[lane*2],    w1 = w4[lane*2+1];
    float s = 0.f;
    s = fmaf(tanhf(a0.x + t0.x), w0.x, s);
    s = fmaf(tanhf(a0.y + t0.y), w0.y, s);
    s = fmaf(tanhf(a0.z + t0.z), w0.z, s);
    s = fmaf(tanhf(a0.w + t0.w), w0.w, s);
    s = fmaf(tanhf(a1.x + t1.x), w1.x, s);
    s = fmaf(tanhf(a1.y + t1.y), w1.y, s);
    s = fmaf(tanhf(a1.z + t1.z), w1.z, s);
    s = fmaf(tanhf(a1.w + t1.w), w1.w, s);
    for (int o = 16; o > 0; o >>= 1) s += __shfl_down_sync(0xffffffffu, s, o);
    if (lane == 0) g_S[tok] = s;
}

// ---------------------------------------------------------------------------
// Per-visit stable sort (softmax->mask->top_k(64 of 64) equivalent)
// ---------------------------------------------------------------------------
__global__ void select_k(const int* __restrict__ masks)
{
    int bl = blockIdx.x, j = threadIdx.x;
    __shared__ float key[64];
    int tok = bl*64 + j;
    float k_ = masks[tok] ? g_S[tok] : neg_inf();
    key[j] = k_; __syncthreads();
    int rank = 0;
    for (int m = 0; m < 64; m++) {
        float o = key[m];
        rank += (o > k_) || (o == k_ && m < j);
    }
    g_selslot[bl*64 + rank] = (bl % LSEQ) * NBLK + j;
}

// ---------------------------------------------------------------------------
// Sequential memory recurrence:
//  - half-warp per candidate (serial depth 8/warp, width-16 reduce tree)
//  - masked keys precomputed once; rank loop scans them as float4s
// Per-candidate reduce order fixed => dup-id bitwise ties preserved.
// ---------------------------------------------------------------------------
__global__ void recur_k(const int* __restrict__ ids, const int* __restrict__ masks,
                        const int* __restrict__ lens)
{
    int b = blockIdx.x, tid = threadIdx.x;
    __shared__ __align__(16) float qw[DM];
    __shared__ int cslot[64], cmask[64];
    __shared__ int nslot[64], nmask[64];
    __shared__ int dslot[128], dmask[128], dcid[128];
    __shared__ float ev[128];
    __shared__ __align__(16) float mk[128];

    if (tid < 64) {
        int slot = g_selslot[(b*LSEQ + 0)*64 + tid];
        cslot[tid] = slot;
        cmask[tid] = masks[b*SLOTS + slot];
    }
    int lb = lens[b];
    __syncthreads();

    const int hw = tid >> 4, hl = tid & 15;    // 16 half-warps of 16 lanes

    for (int t = 1; t < LSEQ; t++) {
        qw[tid] = g_QW[(size_t)(b*LSEQ + t)*DM + tid];
        if (tid < 128) {
            int slot = (tid < 64) ? cslot[tid] : g_selslot[(b*LSEQ + t)*64 + (tid - 64)];
            dslot[tid] = slot;
            dmask[tid] = (tid < 64) ? cmask[tid] : masks[b*SLOTS + slot];
            dcid [tid] = g_tokc[b*SLOTS + slot];
        }
        __syncthreads();

        const float4* q4 = (const float4*)qw;
        float4 qv0 = q4[hl], qv1 = q4[hl+16], qv2 = q4[hl+32], qv3 = q4[hl+48];
        const float4* kv = (const float4*)(g_KV + (size_t)dcid[hw] * DM);
        float4 k0 = kv[hl], k1 = kv[hl+16], k2 = kv[hl+32], k3 = kv[hl+48];
        for (int c = hw; c < 128; c += 16) {
            const bool hasnext = (c + 16 < 128);
            float4 n0, n1, n2, n3;
            if (hasnext) {
                const float4* kn = (const float4*)(g_KV + (size_t)dcid[c + 16] * DM);
                n0 = kn[hl]; n1 = kn[hl+16]; n2 = kn[hl+32]; n3 = kn[hl+48];
            }
            float s = k0.x*qv0.x + k0.y*qv0.y + k0.z*qv0.z + k0.w*qv0.w
                    + k1.x*qv1.x + k1.y*qv1.y + k1.z*qv1.z + k1.w*qv1.w
                    + k2.x*qv2.x + k2.y*qv2.y + k2.z*qv2.z + k2.w*qv2.w
                    + k3.x*qv3.x + k3.y*qv3.y + k3.z*qv3.z + k3.w*qv3.w;
            for (int o = 8; o > 0; o >>= 1) s += __shfl_down_sync(0xffffffffu, s, o, 16);
            if (hl == 0) ev[c] = s;
            if (hasnext) { k0 = n0; k1 = n1; k2 = n2; k3 = n3; }
        }
        __syncthreads();

        if (tid < 128) mk[tid] = dmask[tid] ? ev[tid] : neg_inf();
        __syncthreads();

        if (tid < 128) {
            float k_ = mk[tid];
            int rank = 0;
            const float4* m4 = (const float4*)mk;
#pragma unroll 8
            for (int i = 0; i < 32; i++) {
                float4 o4 = m4[i];
                int mb = i*4;
                rank += (o4.x > k_) || (o4.x == k_ && mb+0 < tid);
                rank += (o4.y > k_) || (o4.y == k_ && mb+1 < tid);
                rank += (o4.z > k_) || (o4.z == k_ && mb+2 < tid);
                rank += (o4.w > k_) || (o4.w == k_ && mb+3 < tid);
            }
            if (rank < 64) { nslot[rank] = dslot[tid]; nmask[rank] = dmask[tid]; }
        }
        __syncthreads();
        if (tid < 64) {
            cslot[tid] = nslot[tid];
            cmask[tid] = nmask[tid];
            if (t == lb - 1) g_fslot[b*64 + tid] = nslot[tid];
        }
        __syncthreads();
    }
}

// ---------------------------------------------------------------------------
// Pools (VT reconstructed as hi+lo; max-pool path, 1e-3 tolerance)
// ---------------------------------------------------------------------------
__global__ void final_k(const float* __restrict__ tv, const int* __restrict__ ids,
                        const int* __restrict__ lens)
{
    int b = blockIdx.x, d = threadIdx.x;
    int lb = lens[b];
    float mx = neg_inf();
    for (int l = 0; l < lb; l++) mx = fmaxf(mx, tv[((size_t)b*LSEQ + l)*DM + d]);
    g_vfin[b*DM + d] = mx;
    float mv = neg_inf();
    for (int m = 0; m < 64; m++) {
        int c = g_tokc[b*SLOTS + g_fslot[b*64 + m]];
        float vt = __bfloat162float(g_VTh[(size_t)c*DM + d])
                 + __bfloat162float(g_VTl[(size_t)c*DM + d]);
        mv = fmaxf(mv, vt);
    }
    g_mfin[b*DM + d] = mv;
    if (d < 64) g_fid[b*64 + d] = ids[b*SLOTS + g_fslot[b*64 + d]];
}

// ---------------------------------------------------------------------------
// Output head + flatten
// ---------------------------------------------------------------------------
__global__ void out_k(const float* __restrict__ ow, const float* __restrict__ ob,
                      float* __restrict__ out, int out_size)
{
    int tid = threadIdx.x;
    if (tid < 32) {
        int b = tid >> 1, o = tid & 1;
        float v = ob[o];
        for (int d = 0; d < DM; d++) v = fmaf(g_vfin[b*DM + d], ow[d*2 + o], v);
        for (int d = 0; d < DM; d++) v = fmaf(g_mfin[b*DM + d], ow[(DM + d)*2 + o], v);
        if (tid < out_size) out[tid] = v;
    }
    for (int i = tid; i < BSZ*64; i += blockDim.x)
        if (32 + i < out_size) out[32 + i] = (float)g_fid[i];
    for (int i = 32 + BSZ*64 + tid; i < out_size; i += blockDim.x)
        out[i] = 0.f;
}

// ---------------------------------------------------------------------------
// Launch
// ---------------------------------------------------------------------------
extern "C" void kernel_launch(void* const* d_in, const int* in_sizes, int n_in,
                              void* d_out, int out_size)
{
    const float* v_all  = (const float*)d_in[0];
    const float* tv_all = (const float*)d_in[1];
    const float* emb    = (const float*)d_in[2];
    const float* w1     = (const float*)d_in[3];
    const float* b1     = (const float*)d_in[4];
    const float* w2     = (const float*)d_in[5];
    const float* b2     = (const float*)d_in[6];
    const float* gam    = (const float*)d_in[7];
    const float* bet    = (const float*)d_in[8];
    const float* wq     = (const float*)d_in[9];
    const float* wk     = (const float*)d_in[10];
    const float* amw1   = (const float*)d_in[11];
    const float* amb1   = (const float*)d_in[12];
    const float* amw2   = (const float*)d_in[13];
    const float* ow     = (const float*)d_in[14];
    const float* ob     = (const float*)d_in[15];
    const int*   itxt   = (const int*)d_in[16];
    const int*   mtxt   = (const int*)d_in[17];
    const int*   lens   = (const int*)d_in[18];
    float* out = (float*)d_out;

    bf16 *pHh, *pHl, *pVTh, *pVTl, *pBh, *pBl;
    float *pKV, *pS2;
    int *pU, *pUL;
    cudaGetSymbolAddress((void**)&pHh,  g_Hh);
    cudaGetSymbolAddress((void**)&pHl,  g_Hl);
    cudaGetSymbolAddress((void**)&pVTh, g_VTh);
    cudaGetSymbolAddress((void**)&pVTl, g_VTl);
    cudaGetSymbolAddress((void**)&pKV,  g_KV);
    cudaGetSymbolAddress((void**)&pS2,  g_S2);
    cudaGetSymbolAddress((void**)&pBh,  g_Bh);
    cudaGetSymbolAddress((void**)&pBl,  g_Bl);
    cudaGetSymbolAddress((void**)&pU,   g_ucnt);
    cudaGetSymbolAddress((void**)&pUL,  g_ulist);

    cudaFuncSetAttribute(gemm_bf, cudaFuncAttributeMaxDynamicSharedMemorySize, GEMM_SMEM);

    // dedup + weight split (parallel scan)
    prep0_k<<<640, 256>>>(w1, w2, wk, amw1 + DM*DM);
    mark_k<<<NTOK/256, 256>>>(itxt);
    scan1_k<<<64, 1024>>>();
    scan2_k<<<1, 64>>>();
    scan3_k<<<64, 1024>>>();

    // GEMM1: relu(emb[gather] @ w1 + b1) -> bf16 planes g_Hh/g_Hl
    gemm_bf<<<dim3(NVOC/128, 2), 512, GEMM_SMEM>>>(
        emb, nullptr, nullptr,
        pBh + OFF_W1, pBl + OFF_W1, nullptr, b1,
        nullptr, nullptr, nullptr, nullptr,
        KD, DH, pUL, 1, pU, 0, pHh, pHl, nullptr, nullptr, 0);

    tokc_k<<<NTOK/256, 256>>>(itxt);
    prep_k<<<NBL, DM>>>(v_all, tv_all, amw1, amb1, wq);

    // GEMM2 + fused LayerNorm: VT = LN(Hplanes @ w2 + b2) -> g_VTh/g_VTl
    gemm_bf<<<dim3(NVOC/128, 1), 512, GEMM_SMEM>>>(
        nullptr, pHh, pHl,
        pBh + OFF_W2, pBl + OFF_W2, nullptr, b2,
        nullptr, nullptr, nullptr, nullptr,
        DH, DM, nullptr, 0, pU, 0, pVTh, pVTl, gam, bet, 1);

    // GEMM3+4 fused: KV = VT @ wk ; S2 = VT @ am_w1[D:]
    gemm_bf<<<dim3(NVOC/128, 2), 512, GEMM_SMEM>>>(
        nullptr, pVTh, pVTl,
        pBh + OFF_WK, pBl + OFF_WK, pKV, nullptr,
        pBh + OFF_AM, pBl + OFF_AM, pS2, nullptr,
        DM, DM, nullptr, 0, pU, 1, nullptr, nullptr, nullptr, nullptr, 0);

    // score + selection + recurrence + pooling + head
    score2_k<<<NTOK/8, 256>>>(amw2);
    select_k<<<NBL, 64>>>(mtxt);
    recur_k<<<BSZ, 256>>>(itxt, mtxt, lens);
    final_k<<<BSZ, DM>>>(tv_all, itxt, lens);
    out_k<<<1, 256>>>(ow, ob, out, out_size);
}